// round 4
// baseline (speedup 1.0000x reference)
#include <cuda_runtime.h>
#include <math.h>

#define G_TOT 2048
#define N100 (64*100*100)
#define N200 (64*200*200)

// ---------------- scratch (static device globals; no allocations) ----------------
__device__ __align__(128) float4 g_p0[2][G_TOT];   // u, v, rx, ry  (rx<0 => culled)
__device__ __align__(128) float4 g_p1[2][G_TOT];   // A, B, C, op
__device__ __align__(128) float g_bev0[N100];
__device__ __align__(128) float g_embT[N100];
__device__ __align__(128) float g_xA[N100];
__device__ __align__(128) float g_xB[N100];
__device__ __align__(128) float g_xC[N100];
__device__ __align__(128) float g_bev1[N200];
__device__ __align__(128) float g_bev1r[N200];
__device__ __align__(128) float g_yu[N200];
__device__ __align__(128) float g_t0[N200];
__device__ __align__(128) float g_yA[N200];
__device__ __align__(128) float g_yB[N200];
__device__ float g_stats[128];                     // per-channel (mu, rstd)

// ---------------- packed f32x2 helpers ----------------
typedef unsigned long long ull;

__device__ __forceinline__ ull pk2(float lo, float hi) {
    ull r;
    asm("mov.b64 %0, {%1,%2};" : "=l"(r) : "f"(lo), "f"(hi));
    return r;
}
__device__ __forceinline__ void unpk2(ull v, float& lo, float& hi) {
    asm("mov.b64 {%0,%1}, %2;" : "=f"(lo), "=f"(hi) : "l"(v));
}
__device__ __forceinline__ ull fma2(ull a, ull b, ull c) {
    ull d;
    asm("fma.rn.f32x2 %0, %1, %2, %3;" : "=l"(d) : "l"(a), "l"(b), "l"(c));
    return d;
}

// ---------------- gaussian preprocessing ----------------
__global__ void prep_k(const float* __restrict__ means, const float* __restrict__ cov,
                       const float* __restrict__ opac)
{
    int g = blockIdx.x * blockDim.x + threadIdx.x;
    if (g >= G_TOT) return;
    float mx = means[g*3+0], my = means[g*3+1], mz = means[g*3+2];
    bool pos = (mx >= -50.f) && (mx <= 50.f) && (my >= -50.f) && (my <= 50.f)
            && (mz >= -4.f)  && (mz <= 4.f);
    float c0 = cov[g*6+0], c1 = cov[g*6+1], c3 = cov[g*6+3];
    #pragma unroll
    for (int s = 0; s < 2; s++) {
        float H  = (s == 0) ? 100.f : 200.f;
        float sh = (s == 0) ? 1.f   : 2.f;
        float op = opac[g*2+s];
        bool mk = pos && (op > 0.05f);
        float u = -sh*my + 0.5f*H;
        float v = -sh*mx + 0.5f*H;
        float a  = sh*sh*c3 + 0.3f;
        float cc = sh*sh*c0 + 0.3f;
        float bb = sh*sh*c1;
        float det = fmaxf(a*cc - bb*bb, 1e-8f);
        float inv = 1.f/det;
        float A = cc*inv, Bc = -bb*inv, C = a*inv;
        float ct = logf(255.f*fmaxf(op, 1e-20f));
        float rx = sqrtf(fmaxf(2.f*ct*a , 0.f));
        float ry = sqrtf(fmaxf(2.f*ct*cc, 0.f));
        if (!mk) rx = -1.f;
        g_p0[s][g] = make_float4(u, v, rx, ry);
        g_p1[s][g] = make_float4(A, Bc, C, op);
    }
}

// ---------------- num_g ----------------
__global__ void numg_k(const float* __restrict__ means, const float* __restrict__ opac,
                       float* __restrict__ out, int out_size)
{
    __shared__ int red[256];
    int tid = threadIdx.x;
    int cnt = 0;
    for (int g = tid; g < G_TOT; g += 256) {
        float mx = means[g*3], my = means[g*3+1], mz = means[g*3+2];
        bool pos = (mx >= -50.f) && (mx <= 50.f) && (my >= -50.f) && (my <= 50.f)
                && (mz >= -4.f) && (mz <= 4.f);
        if (pos) {
            if (opac[g*2+0] > 0.05f) cnt++;
            if (opac[g*2+1] > 0.05f) cnt++;
        }
    }
    red[tid] = cnt; __syncthreads();
    for (int st = 128; st > 0; st >>= 1) {
        if (tid < st) red[tid] += red[tid+st];
        __syncthreads();
    }
    if (tid == 0 && out_size > 64*200*200) out[64*200*200] = (float)red[0];
}

// ---------------- tiled ordered splatting (16x16 tiles, 256 thr) ----------------
__global__ void render_k(int s, const float* __restrict__ feats,
                         float* __restrict__ out, int H)
{
    const int W = H;
    __shared__ int s_list[G_TOT];
    __shared__ int s_wcnt[8];
    int tid = threadIdx.x;
    int lane = tid & 31, wid = tid >> 5;
    int tx0 = blockIdx.x * 16, ty0 = blockIdx.y * 16;
    float xmin = (float)tx0, xmax = (float)min(tx0 + 15, W - 1);
    float ymin = (float)ty0, ymax = (float)min(ty0 + 15, H - 1);

    // phase 1: build index-ordered list of overlapping gaussians
    int num = 0;
    for (int base = 0; base < G_TOT; base += 256) {
        int g = base + tid;
        float4 q = g_p0[s][g];
        bool ok = (q.z >= 0.f) &&
                  (q.x + q.z >= xmin) && (q.x - q.z <= xmax) &&
                  (q.y + q.w >= ymin) && (q.y - q.w <= ymax);
        unsigned m = __ballot_sync(0xffffffffu, ok);
        if (lane == 0) s_wcnt[wid] = __popc(m);
        __syncthreads();
        int off = num + __popc(m & ((1u << lane) - 1u));
        int tot = 0;
        #pragma unroll
        for (int w2 = 0; w2 < 8; w2++) {
            int c = s_wcnt[w2];
            if (w2 < wid) off += c;
            tot += c;
        }
        if (ok) s_list[off] = g;
        num += tot;
        __syncthreads();
    }

    // phase 2: per-pixel front-to-back compositing in index order
    int px = tx0 + (tid & 15);
    int py = ty0 + (tid >> 4);
    float fx = (float)px, fy = (float)py;
    float T = 1.f;
    float acc[64];
    #pragma unroll
    for (int d = 0; d < 64; d++) acc[d] = 0.f;

    for (int i = 0; i < num; i++) {
        int g = s_list[i];
        float4 q = g_p0[s][g];
        float4 r = g_p1[s][g];
        float dx = q.x - fx, dy = q.y - fy;
        float power = -0.5f*(r.x*dx*dx + r.z*dy*dy) - r.y*dx*dy;
        float alpha = fminf(r.w * expf(power), 0.99f);
        if (alpha >= (1.f/255.f) && power <= 0.f) {
            float wg = alpha * T;
            T *= (1.f - alpha);
            const float4* f4 = (const float4*)(feats + (size_t)g * 64);
            #pragma unroll
            for (int j = 0; j < 16; j++) {
                float4 fv = __ldg(f4 + j);
                acc[4*j+0] += wg*fv.x;
                acc[4*j+1] += wg*fv.y;
                acc[4*j+2] += wg*fv.z;
                acc[4*j+3] += wg*fv.w;
            }
        }
    }
    if (px < W && py < H) {
        #pragma unroll
        for (int d = 0; d < 64; d++) out[d*H*W + py*W + px] = acc[d];
    }
}

// ---------------- bev_emb transpose: [p][d] -> [d][p] ----------------
__global__ void transpose_emb_k(const float* __restrict__ emb, float* __restrict__ out)
{
    int idx = blockIdx.x * 256 + threadIdx.x;
    if (idx >= 64*10000) return;
    int d = idx / 10000;
    int p = idx - d * 10000;
    out[idx] = emb[p*64 + d];
}

// ---------------- direct conv3x3, 64->64, f32x2 co-pair packed ----------------
// block: 256 thr; tile 32x16 spatial x 16 output channels;
// thread: 4 co-pairs (f32x2) x 4 px
#define CTW 32
#define CTH 16
#define CICH 8
#define COG 16

__global__ void __launch_bounds__(256, 2)
conv3x3_k(const float* __restrict__ in, const float* __restrict__ wgt,
          const float* __restrict__ add, float* __restrict__ out,
          int H, int W, int relu)
{
    __shared__ float  s_in[CICH][CTH+2][CTW+3];   // stride 35: conflict-free reads
    __shared__ float2 s_w2[CICH][9][COG/2];       // {w[2cp], w[2cp+1]}

    int tid  = threadIdx.x;
    int half = tid >> 7;          // 0/1 -> co-pair offset 4*half
    int quad = tid & 127;
    int qx = quad & 7;            // 4-px strip: x = x0 + qx*4 + p
    int qy = quad >> 3;           // row within tile
    int x0 = blockIdx.x * CTW;
    int y0 = blockIdx.y * CTH;
    int co0 = blockIdx.z * COG;
    int HW = H * W;

    ull acc2[4][4];
    #pragma unroll
    for (int i = 0; i < 4; i++)
        #pragma unroll
        for (int j = 0; j < 4; j++) acc2[i][j] = 0ull;

    for (int cb = 0; cb < 64; cb += CICH) {
        const int INEL = CICH * (CTH+2) * (CTW+2);   // 8*18*34
        for (int i = tid; i < INEL; i += 256) {
            int ci  = i / (18*34);
            int rem = i - ci * (18*34);
            int r = rem / 34;
            int c = rem - r * 34;
            int gy = y0 - 1 + r;
            int gx = x0 - 1 + c;
            float v = 0.f;
            if (gy >= 0 && gy < H && gx >= 0 && gx < W)
                v = in[(cb+ci)*HW + gy*W + gx];
            s_in[ci][r][c] = v;
        }
        const int WEL = CICH * 9 * (COG/2);          // 576 float2
        for (int i = tid; i < WEL; i += 256) {
            int cp   = i & 7;
            int rest = i >> 3;
            int k  = rest % 9;
            int ci = rest / 9;
            float2 v;
            v.x = wgt[(co0 + 2*cp    )*576 + (cb+ci)*9 + k];
            v.y = wgt[(co0 + 2*cp + 1)*576 + (cb+ci)*9 + k];
            s_w2[ci][k][cp] = v;
        }
        __syncthreads();

        #pragma unroll 2
        for (int ci = 0; ci < CICH; ci++) {
            ull iv2[3][6];
            #pragma unroll
            for (int r = 0; r < 3; r++)
                #pragma unroll
                for (int c = 0; c < 6; c++) {
                    float v = s_in[ci][qy + r][qx*4 + c];
                    iv2[r][c] = pk2(v, v);
                }
            #pragma unroll
            for (int cpl = 0; cpl < 4; cpl++) {
                int cpg = half*4 + cpl;
                ull w2[9];
                #pragma unroll
                for (int k = 0; k < 9; k++) {
                    float2 wv = s_w2[ci][k][cpg];
                    w2[k] = *(ull*)&wv;
                }
                #pragma unroll
                for (int p = 0; p < 4; p++) {
                    ull sum = acc2[cpl][p];
                    #pragma unroll
                    for (int ky = 0; ky < 3; ky++)
                        #pragma unroll
                        for (int kx = 0; kx < 3; kx++)
                            sum = fma2(w2[ky*3+kx], iv2[ky][p+kx], sum);
                    acc2[cpl][p] = sum;
                }
            }
        }
        __syncthreads();
    }

    int py  = y0 + qy;
    int pxb = x0 + qx * 4;
    if (py < H) {
        #pragma unroll
        for (int p = 0; p < 4; p++) {
            int x = pxb + p;
            if (x < W) {
                #pragma unroll
                for (int cpl = 0; cpl < 4; cpl++) {
                    int c0 = co0 + 2*(half*4 + cpl);
                    float v0, v1;
                    unpk2(acc2[cpl][p], v0, v1);
                    if (add) { v0 += add[c0*HW + py*W + x]; v1 += add[(c0+1)*HW + py*W + x]; }
                    if (relu) { v0 = fmaxf(v0, 0.f); v1 = fmaxf(v1, 0.f); }
                    out[c0*HW + py*W + x]     = v0;
                    out[(c0+1)*HW + py*W + x] = v1;
                }
            }
        }
    }
}

// ---------------- bilinear 2x upsample (jax half-pixel + edge clamp) ----------------
__global__ void upsample_k(const float* __restrict__ in, float* __restrict__ out)
{
    int idx = blockIdx.x * 256 + threadIdx.x;
    if (idx >= 64*200*200) return;
    int x = idx % 200;
    int t = idx / 200;
    int y = t % 200;
    int c = t / 200;
    float sx = 0.5f*x - 0.25f;
    float sy = 0.5f*y - 0.25f;
    float fx = floorf(sx), fy = floorf(sy);
    float tx = sx - fx, ty = sy - fy;
    int x0 = max((int)fx, 0), x1 = min((int)fx + 1, 99);
    int y0 = max((int)fy, 0), y1 = min((int)fy + 1, 99);
    const float* p = in + c * 10000;
    float v00 = p[y0*100+x0], v01 = p[y0*100+x1];
    float v10 = p[y1*100+x0], v11 = p[y1*100+x1];
    out[idx] = (1.f-ty)*((1.f-tx)*v00 + tx*v01) + ty*((1.f-tx)*v10 + tx*v11);
}

// ---------------- instance norm ----------------
__global__ void in_reduce_k(const float* __restrict__ x)
{
    int c = blockIdx.x;
    const float* p = x + c * 40000;
    float s = 0.f, s2 = 0.f;
    for (int i = threadIdx.x; i < 40000; i += 256) { float v = p[i]; s += v; s2 += v*v; }
    __shared__ float rs[256], rq[256];
    rs[threadIdx.x] = s; rq[threadIdx.x] = s2;
    __syncthreads();
    for (int st = 128; st > 0; st >>= 1) {
        if (threadIdx.x < st) { rs[threadIdx.x] += rs[threadIdx.x+st]; rq[threadIdx.x] += rq[threadIdx.x+st]; }
        __syncthreads();
    }
    if (threadIdx.x == 0) {
        float mu  = rs[0] * (1.f/40000.f);
        float var = rq[0] * (1.f/40000.f) - mu*mu;
        g_stats[c*2]   = mu;
        g_stats[c*2+1] = 1.f/sqrtf(var + 1e-5f);
    }
}

__global__ void in_apply_k(const float* __restrict__ t, const float* __restrict__ add,
                           float* __restrict__ out)
{
    int idx = blockIdx.x * 256 + threadIdx.x;
    if (idx >= 64*40000) return;
    int c = idx / 40000;
    out[idx] = (t[idx] - g_stats[c*2]) * g_stats[c*2+1] + add[idx];
}

// ---------------- launch ----------------
extern "C" void kernel_launch(void* const* d_in, const int* in_sizes, int n_in,
                              void* d_out, int out_size)
{
    const float* features = (const float*)d_in[0];
    const float* means    = (const float*)d_in[1];
    const float* cov      = (const float*)d_in[2];
    const float* opac     = (const float*)d_in[3];
    const float* emb      = (const float*)d_in[4];
    const float* conv1w   = (const float*)d_in[5];
    const float* blkw     = (const float*)d_in[6];
    const float* upw      = (const float*)d_in[7];
    float* out = (float*)d_out;

    float *bev0,*embT,*xA,*xB,*xC,*bev1,*bev1r,*yu,*t0,*yA,*yB;
    cudaGetSymbolAddress((void**)&bev0,  g_bev0);
    cudaGetSymbolAddress((void**)&embT,  g_embT);
    cudaGetSymbolAddress((void**)&xA,    g_xA);
    cudaGetSymbolAddress((void**)&xB,    g_xB);
    cudaGetSymbolAddress((void**)&xC,    g_xC);
    cudaGetSymbolAddress((void**)&bev1,  g_bev1);
    cudaGetSymbolAddress((void**)&bev1r, g_bev1r);
    cudaGetSymbolAddress((void**)&yu,    g_yu);
    cudaGetSymbolAddress((void**)&t0,    g_t0);
    cudaGetSymbolAddress((void**)&yA,    g_yA);
    cudaGetSymbolAddress((void**)&yB,    g_yB);

    prep_k<<<8, 256>>>(means, cov, opac);
    numg_k<<<1, 256>>>(means, opac, out, out_size);
    render_k<<<dim3(7,7),   256>>>(0, features, bev0, 100);
    render_k<<<dim3(13,13), 256>>>(1, features, bev1, 200);
    transpose_emb_k<<<2500, 256>>>(emb, embT);

    dim3 cb(256);
    dim3 g100(4, 7, 4);    // ceil(100/32), ceil(100/16), 64/16
    dim3 g200(7, 13, 4);   // ceil(200/32), ceil(200/16), 64/16

    // stage 0 @100x100
    conv3x3_k<<<g100, cb>>>(bev0, conv1w + 0,        embT,    xA, 100, 100, 0);
    conv3x3_k<<<g100, cb>>>(xA,   blkw + 0*36864,    nullptr, xB, 100, 100, 1);
    conv3x3_k<<<g100, cb>>>(xB,   blkw + 1*36864,    xA,      xC, 100, 100, 1);
    conv3x3_k<<<g100, cb>>>(xC,   blkw + 2*36864,    nullptr, xA, 100, 100, 1);
    conv3x3_k<<<g100, cb>>>(xA,   blkw + 3*36864,    xC,      xB, 100, 100, 1);

    // stage 1 @200x200
    conv3x3_k<<<g200, cb>>>(bev1, conv1w + 36864,    nullptr, bev1r, 200, 200, 0);
    upsample_k<<<10000, 256>>>(xB, yu);
    conv3x3_k<<<g200, cb>>>(yu,   upw,               nullptr, t0,    200, 200, 0);
    in_reduce_k<<<64, 256>>>(t0);
    in_apply_k<<<10000, 256>>>(t0, bev1r, yA);
    conv3x3_k<<<g200, cb>>>(yA,   blkw + 4*36864,    nullptr, yB,  200, 200, 1);
    conv3x3_k<<<g200, cb>>>(yB,   blkw + 5*36864,    yA,      t0,  200, 200, 1);
    conv3x3_k<<<g200, cb>>>(t0,   blkw + 6*36864,    nullptr, yB,  200, 200, 1);
    conv3x3_k<<<g200, cb>>>(yB,   blkw + 7*36864,    t0,      out, 200, 200, 1);
}

// round 5
// speedup vs baseline: 1.0109x; 1.0109x over previous
#include <cuda_runtime.h>
#include <math.h>

#define G_TOT 2048
#define N100 (64*100*100)
#define N200 (64*200*200)

// ---------------- scratch (static device globals; no allocations) ----------------
__device__ __align__(128) float4 g_p0[2][G_TOT];   // u, v, rx, ry  (rx<0 => culled)
__device__ __align__(128) float4 g_p1[2][G_TOT];   // A, B, C, op
__device__ __align__(128) float g_bev0[N100];
__device__ __align__(128) float g_embT[N100];
__device__ __align__(128) float g_xA[N100];
__device__ __align__(128) float g_xB[N100];
__device__ __align__(128) float g_xC[N100];
__device__ __align__(128) float g_bev1[N200];
__device__ __align__(128) float g_bev1r[N200];
__device__ __align__(128) float g_yu[N200];
__device__ __align__(128) float g_t0[N200];
__device__ __align__(128) float g_yA[N200];
__device__ __align__(128) float g_yB[N200];
__device__ float g_stats[128];                     // per-channel (mu, rstd)

// ---------------- packed f32x2 helpers ----------------
typedef unsigned long long ull;

__device__ __forceinline__ ull pk2(float lo, float hi) {
    ull r;
    asm("mov.b64 %0, {%1,%2};" : "=l"(r) : "f"(lo), "f"(hi));
    return r;
}
__device__ __forceinline__ void unpk2(ull v, float& lo, float& hi) {
    asm("mov.b64 {%0,%1}, %2;" : "=f"(lo), "=f"(hi) : "l"(v));
}
__device__ __forceinline__ ull fma2(ull a, ull b, ull c) {
    ull d;
    asm("fma.rn.f32x2 %0, %1, %2, %3;" : "=l"(d) : "l"(a), "l"(b), "l"(c));
    return d;
}

// ---------------- gaussian preprocessing ----------------
__global__ void prep_k(const float* __restrict__ means, const float* __restrict__ cov,
                       const float* __restrict__ opac)
{
    int g = blockIdx.x * blockDim.x + threadIdx.x;
    if (g >= G_TOT) return;
    float mx = means[g*3+0], my = means[g*3+1], mz = means[g*3+2];
    bool pos = (mx >= -50.f) && (mx <= 50.f) && (my >= -50.f) && (my <= 50.f)
            && (mz >= -4.f)  && (mz <= 4.f);
    float c0 = cov[g*6+0], c1 = cov[g*6+1], c3 = cov[g*6+3];
    #pragma unroll
    for (int s = 0; s < 2; s++) {
        float H  = (s == 0) ? 100.f : 200.f;
        float sh = (s == 0) ? 1.f   : 2.f;
        float op = opac[g*2+s];
        bool mk = pos && (op > 0.05f);
        float u = -sh*my + 0.5f*H;
        float v = -sh*mx + 0.5f*H;
        float a  = sh*sh*c3 + 0.3f;
        float cc = sh*sh*c0 + 0.3f;
        float bb = sh*sh*c1;
        float det = fmaxf(a*cc - bb*bb, 1e-8f);
        float inv = 1.f/det;
        float A = cc*inv, Bc = -bb*inv, C = a*inv;
        float ct = logf(255.f*fmaxf(op, 1e-20f));
        float rx = sqrtf(fmaxf(2.f*ct*a , 0.f));
        float ry = sqrtf(fmaxf(2.f*ct*cc, 0.f));
        if (!mk) rx = -1.f;
        g_p0[s][g] = make_float4(u, v, rx, ry);
        g_p1[s][g] = make_float4(A, Bc, C, op);
    }
}

// ---------------- num_g ----------------
__global__ void numg_k(const float* __restrict__ means, const float* __restrict__ opac,
                       float* __restrict__ out, int out_size)
{
    __shared__ int red[256];
    int tid = threadIdx.x;
    int cnt = 0;
    for (int g = tid; g < G_TOT; g += 256) {
        float mx = means[g*3], my = means[g*3+1], mz = means[g*3+2];
        bool pos = (mx >= -50.f) && (mx <= 50.f) && (my >= -50.f) && (my <= 50.f)
                && (mz >= -4.f) && (mz <= 4.f);
        if (pos) {
            if (opac[g*2+0] > 0.05f) cnt++;
            if (opac[g*2+1] > 0.05f) cnt++;
        }
    }
    red[tid] = cnt; __syncthreads();
    for (int st = 128; st > 0; st >>= 1) {
        if (tid < st) red[tid] += red[tid+st];
        __syncthreads();
    }
    if (tid == 0 && out_size > 64*200*200) out[64*200*200] = (float)red[0];
}

// ---------------- tiled ordered splatting (16x16 tiles, 256 thr) ----------------
__global__ void render_k(int s, const float* __restrict__ feats,
                         float* __restrict__ out, int H)
{
    const int W = H;
    __shared__ int s_list[G_TOT];
    __shared__ int s_wcnt[8];
    int tid = threadIdx.x;
    int lane = tid & 31, wid = tid >> 5;
    int tx0 = blockIdx.x * 16, ty0 = blockIdx.y * 16;
    float xmin = (float)tx0, xmax = (float)min(tx0 + 15, W - 1);
    float ymin = (float)ty0, ymax = (float)min(ty0 + 15, H - 1);

    // phase 1: build index-ordered list of overlapping gaussians
    int num = 0;
    for (int base = 0; base < G_TOT; base += 256) {
        int g = base + tid;
        float4 q = g_p0[s][g];
        bool ok = (q.z >= 0.f) &&
                  (q.x + q.z >= xmin) && (q.x - q.z <= xmax) &&
                  (q.y + q.w >= ymin) && (q.y - q.w <= ymax);
        unsigned m = __ballot_sync(0xffffffffu, ok);
        if (lane == 0) s_wcnt[wid] = __popc(m);
        __syncthreads();
        int off = num + __popc(m & ((1u << lane) - 1u));
        int tot = 0;
        #pragma unroll
        for (int w2 = 0; w2 < 8; w2++) {
            int c = s_wcnt[w2];
            if (w2 < wid) off += c;
            tot += c;
        }
        if (ok) s_list[off] = g;
        num += tot;
        __syncthreads();
    }

    // phase 2: per-pixel front-to-back compositing in index order
    int px = tx0 + (tid & 15);
    int py = ty0 + (tid >> 4);
    float fx = (float)px, fy = (float)py;
    float T = 1.f;
    float acc[64];
    #pragma unroll
    for (int d = 0; d < 64; d++) acc[d] = 0.f;

    for (int i = 0; i < num; i++) {
        int g = s_list[i];
        float4 q = g_p0[s][g];
        float4 r = g_p1[s][g];
        float dx = q.x - fx, dy = q.y - fy;
        float power = -0.5f*(r.x*dx*dx + r.z*dy*dy) - r.y*dx*dy;
        float alpha = fminf(r.w * expf(power), 0.99f);
        if (alpha >= (1.f/255.f) && power <= 0.f) {
            float wg = alpha * T;
            T *= (1.f - alpha);
            const float4* f4 = (const float4*)(feats + (size_t)g * 64);
            #pragma unroll
            for (int j = 0; j < 16; j++) {
                float4 fv = __ldg(f4 + j);
                acc[4*j+0] += wg*fv.x;
                acc[4*j+1] += wg*fv.y;
                acc[4*j+2] += wg*fv.z;
                acc[4*j+3] += wg*fv.w;
            }
        }
    }
    if (px < W && py < H) {
        #pragma unroll
        for (int d = 0; d < 64; d++) out[d*H*W + py*W + px] = acc[d];
    }
}

// ---------------- bev_emb transpose: [p][d] -> [d][p] ----------------
__global__ void transpose_emb_k(const float* __restrict__ emb, float* __restrict__ out)
{
    int idx = blockIdx.x * 256 + threadIdx.x;
    if (idx >= 64*10000) return;
    int d = idx / 10000;
    int p = idx - d * 10000;
    out[idx] = emb[p*64 + d];
}

// ---------------- direct conv3x3, 64->64, f32x2 co-pair packed ----------------
// block: 256 thr; tile 32x16 spatial x 16 output channels;
// thread: 4 co-pairs (f32x2) x 4 px
#define CTW 32
#define CTH 16
#define CICH 8
#define COG 16

__global__ void __launch_bounds__(256, 2)
conv3x3_k(const float* __restrict__ in, const float* __restrict__ wgt,
          const float* __restrict__ add, float* __restrict__ out,
          int H, int W, int relu)
{
    __shared__ float  s_in[CICH][CTH+2][CTW+3];   // stride 35: conflict-free reads
    __shared__ float2 s_w2[CICH][9][COG/2];       // {w[2cp], w[2cp+1]}

    int tid  = threadIdx.x;
    int half = tid >> 7;          // 0/1 -> co-pair offset 4*half
    int quad = tid & 127;
    int qx = quad & 7;            // 4-px strip: x = x0 + qx*4 + p
    int qy = quad >> 3;           // row within tile
    int x0 = blockIdx.x * CTW;
    int y0 = blockIdx.y * CTH;
    int co0 = blockIdx.z * COG;
    int HW = H * W;

    ull acc2[4][4];
    #pragma unroll
    for (int i = 0; i < 4; i++)
        #pragma unroll
        for (int j = 0; j < 4; j++) acc2[i][j] = 0ull;

    for (int cb = 0; cb < 64; cb += CICH) {
        const int INEL = CICH * (CTH+2) * (CTW+2);   // 8*18*34
        for (int i = tid; i < INEL; i += 256) {
            int ci  = i / (18*34);
            int rem = i - ci * (18*34);
            int r = rem / 34;
            int c = rem - r * 34;
            int gy = y0 - 1 + r;
            int gx = x0 - 1 + c;
            float v = 0.f;
            if (gy >= 0 && gy < H && gx >= 0 && gx < W)
                v = in[(cb+ci)*HW + gy*W + gx];
            s_in[ci][r][c] = v;
        }
        const int WEL = CICH * 9 * (COG/2);          // 576 float2
        for (int i = tid; i < WEL; i += 256) {
            int cp   = i & 7;
            int rest = i >> 3;
            int k  = rest % 9;
            int ci = rest / 9;
            float2 v;
            v.x = wgt[(co0 + 2*cp    )*576 + (cb+ci)*9 + k];
            v.y = wgt[(co0 + 2*cp + 1)*576 + (cb+ci)*9 + k];
            s_w2[ci][k][cp] = v;
        }
        __syncthreads();

        #pragma unroll 2
        for (int ci = 0; ci < CICH; ci++) {
            ull iv2[3][6];
            #pragma unroll
            for (int r = 0; r < 3; r++)
                #pragma unroll
                for (int c = 0; c < 6; c++) {
                    float v = s_in[ci][qy + r][qx*4 + c];
                    iv2[r][c] = pk2(v, v);
                }
            #pragma unroll
            for (int cpl = 0; cpl < 4; cpl++) {
                int cpg = half*4 + cpl;
                ull w2[9];
                #pragma unroll
                for (int k = 0; k < 9; k++) {
                    float2 wv = s_w2[ci][k][cpg];
                    w2[k] = *(ull*)&wv;
                }
                #pragma unroll
                for (int p = 0; p < 4; p++) {
                    ull sum = acc2[cpl][p];
                    #pragma unroll
                    for (int ky = 0; ky < 3; ky++)
                        #pragma unroll
                        for (int kx = 0; kx < 3; kx++)
                            sum = fma2(w2[ky*3+kx], iv2[ky][p+kx], sum);
                    acc2[cpl][p] = sum;
                }
            }
        }
        __syncthreads();
    }

    int py  = y0 + qy;
    int pxb = x0 + qx * 4;
    if (py < H) {
        #pragma unroll
        for (int p = 0; p < 4; p++) {
            int x = pxb + p;
            if (x < W) {
                #pragma unroll
                for (int cpl = 0; cpl < 4; cpl++) {
                    int c0 = co0 + 2*(half*4 + cpl);
                    float v0, v1;
                    unpk2(acc2[cpl][p], v0, v1);
                    if (add) { v0 += add[c0*HW + py*W + x]; v1 += add[(c0+1)*HW + py*W + x]; }
                    if (relu) { v0 = fmaxf(v0, 0.f); v1 = fmaxf(v1, 0.f); }
                    out[c0*HW + py*W + x]     = v0;
                    out[(c0+1)*HW + py*W + x] = v1;
                }
            }
        }
    }
}

// ---------------- bilinear 2x upsample (jax half-pixel + edge clamp) ----------------
__global__ void upsample_k(const float* __restrict__ in, float* __restrict__ out)
{
    int idx = blockIdx.x * 256 + threadIdx.x;
    if (idx >= 64*200*200) return;
    int x = idx % 200;
    int t = idx / 200;
    int y = t % 200;
    int c = t / 200;
    float sx = 0.5f*x - 0.25f;
    float sy = 0.5f*y - 0.25f;
    float fx = floorf(sx), fy = floorf(sy);
    float tx = sx - fx, ty = sy - fy;
    int x0 = max((int)fx, 0), x1 = min((int)fx + 1, 99);
    int y0 = max((int)fy, 0), y1 = min((int)fy + 1, 99);
    const float* p = in + c * 10000;
    float v00 = p[y0*100+x0], v01 = p[y0*100+x1];
    float v10 = p[y1*100+x0], v11 = p[y1*100+x1];
    out[idx] = (1.f-ty)*((1.f-tx)*v00 + tx*v01) + ty*((1.f-tx)*v10 + tx*v11);
}

// ---------------- instance norm ----------------
__global__ void in_reduce_k(const float* __restrict__ x)
{
    int c = blockIdx.x;
    const float* p = x + c * 40000;
    float s = 0.f, s2 = 0.f;
    for (int i = threadIdx.x; i < 40000; i += 256) { float v = p[i]; s += v; s2 += v*v; }
    __shared__ float rs[256], rq[256];
    rs[threadIdx.x] = s; rq[threadIdx.x] = s2;
    __syncthreads();
    for (int st = 128; st > 0; st >>= 1) {
        if (threadIdx.x < st) { rs[threadIdx.x] += rs[threadIdx.x+st]; rq[threadIdx.x] += rq[threadIdx.x+st]; }
        __syncthreads();
    }
    if (threadIdx.x == 0) {
        float mu  = rs[0] * (1.f/40000.f);
        float var = rq[0] * (1.f/40000.f) - mu*mu;
        g_stats[c*2]   = mu;
        g_stats[c*2+1] = 1.f/sqrtf(var + 1e-5f);
    }
}

__global__ void in_apply_k(const float* __restrict__ t, const float* __restrict__ add,
                           float* __restrict__ out)
{
    int idx = blockIdx.x * 256 + threadIdx.x;
    if (idx >= 64*40000) return;
    int c = idx / 40000;
    out[idx] = (t[idx] - g_stats[c*2]) * g_stats[c*2+1] + add[idx];
}

// ---------------- launch ----------------
extern "C" void kernel_launch(void* const* d_in, const int* in_sizes, int n_in,
                              void* d_out, int out_size)
{
    const float* features = (const float*)d_in[0];
    const float* means    = (const float*)d_in[1];
    const float* cov      = (const float*)d_in[2];
    const float* opac     = (const float*)d_in[3];
    const float* emb      = (const float*)d_in[4];
    const float* conv1w   = (const float*)d_in[5];
    const float* blkw     = (const float*)d_in[6];
    const float* upw      = (const float*)d_in[7];
    float* out = (float*)d_out;

    float *bev0,*embT,*xA,*xB,*xC,*bev1,*bev1r,*yu,*t0,*yA,*yB;
    cudaGetSymbolAddress((void**)&bev0,  g_bev0);
    cudaGetSymbolAddress((void**)&embT,  g_embT);
    cudaGetSymbolAddress((void**)&xA,    g_xA);
    cudaGetSymbolAddress((void**)&xB,    g_xB);
    cudaGetSymbolAddress((void**)&xC,    g_xC);
    cudaGetSymbolAddress((void**)&bev1,  g_bev1);
    cudaGetSymbolAddress((void**)&bev1r, g_bev1r);
    cudaGetSymbolAddress((void**)&yu,    g_yu);
    cudaGetSymbolAddress((void**)&t0,    g_t0);
    cudaGetSymbolAddress((void**)&yA,    g_yA);
    cudaGetSymbolAddress((void**)&yB,    g_yB);

    prep_k<<<8, 256>>>(means, cov, opac);
    numg_k<<<1, 256>>>(means, opac, out, out_size);
    render_k<<<dim3(7,7),   256>>>(0, features, bev0, 100);
    render_k<<<dim3(13,13), 256>>>(1, features, bev1, 200);
    transpose_emb_k<<<2500, 256>>>(emb, embT);

    dim3 cb(256);
    dim3 g100(4, 7, 4);    // ceil(100/32), ceil(100/16), 64/16
    dim3 g200(7, 13, 4);   // ceil(200/32), ceil(200/16), 64/16

    // stage 0 @100x100
    conv3x3_k<<<g100, cb>>>(bev0, conv1w + 0,        embT,    xA, 100, 100, 0);
    conv3x3_k<<<g100, cb>>>(xA,   blkw + 0*36864,    nullptr, xB, 100, 100, 1);
    conv3x3_k<<<g100, cb>>>(xB,   blkw + 1*36864,    xA,      xC, 100, 100, 1);
    conv3x3_k<<<g100, cb>>>(xC,   blkw + 2*36864,    nullptr, xA, 100, 100, 1);
    conv3x3_k<<<g100, cb>>>(xA,   blkw + 3*36864,    xC,      xB, 100, 100, 1);

    // stage 1 @200x200
    conv3x3_k<<<g200, cb>>>(bev1, conv1w + 36864,    nullptr, bev1r, 200, 200, 0);
    upsample_k<<<10000, 256>>>(xB, yu);
    conv3x3_k<<<g200, cb>>>(yu,   upw,               nullptr, t0,    200, 200, 0);
    in_reduce_k<<<64, 256>>>(t0);
    in_apply_k<<<10000, 256>>>(t0, bev1r, yA);
    conv3x3_k<<<g200, cb>>>(yA,   blkw + 4*36864,    nullptr, yB,  200, 200, 1);
    conv3x3_k<<<g200, cb>>>(yB,   blkw + 5*36864,    yA,      t0,  200, 200, 1);
    conv3x3_k<<<g200, cb>>>(t0,   blkw + 6*36864,    nullptr, yB,  200, 200, 1);
    conv3x3_k<<<g200, cb>>>(yB,   blkw + 7*36864,    t0,      out, 200, 200, 1);
}

// round 7
// speedup vs baseline: 1.8432x; 1.8232x over previous
#include <cuda_runtime.h>
#include <math.h>

#define G_TOT 2048

// ---------------- scratch (zero-initialized globals; halos never written) ----------------
__device__ __align__(128) float4 g_p0[2][G_TOT];
__device__ __align__(128) float4 g_p1[2][G_TOT];
__device__ __align__(128) float g_s0a[102*102*64];
__device__ __align__(128) float g_s0b[102*102*64];
__device__ __align__(128) float g_s0c[102*102*64];
__device__ __align__(128) float g_s0d[102*102*64];
__device__ __align__(128) float g_b1[202*202*64];
__device__ __align__(128) float g_b2[202*202*64];
__device__ __align__(128) float g_b3[202*202*64];
__device__ __align__(128) float g_b4[202*202*64];
__device__ __align__(128) float g_wh[11*9*64*64];
__device__ __align__(128) float g_wl[11*9*64*64];
__device__ __align__(128) float g_part[202*128];
__device__ float g_stats[128];

__device__ __forceinline__ unsigned t32(float x) {
    unsigned r; asm("cvt.rna.tf32.f32 %0, %1;" : "=r"(r) : "f"(x)); return r;
}
#define MMA_TF32(c0,c1,c2,c3,a0,a1,a2,a3,b0,b1) \
  asm("mma.sync.aligned.m16n8k8.row.col.f32.tf32.tf32.f32 " \
      "{%0,%1,%2,%3}, {%4,%5,%6,%7}, {%8,%9}, {%0,%1,%2,%3};" \
      : "+f"(c0),"+f"(c1),"+f"(c2),"+f"(c3) \
      : "r"(a0),"r"(a1),"r"(a2),"r"(a3),"r"(b0),"r"(b1))

// ---------------- gaussian preprocessing ----------------
__global__ void prep_k(const float* __restrict__ means, const float* __restrict__ cov,
                       const float* __restrict__ opac)
{
    int g = blockIdx.x * blockDim.x + threadIdx.x;
    if (g >= G_TOT) return;
    float mx = means[g*3+0], my = means[g*3+1], mz = means[g*3+2];
    bool pos = (mx >= -50.f) && (mx <= 50.f) && (my >= -50.f) && (my <= 50.f)
            && (mz >= -4.f)  && (mz <= 4.f);
    float c0 = cov[g*6+0], c1 = cov[g*6+1], c3 = cov[g*6+3];
    #pragma unroll
    for (int s = 0; s < 2; s++) {
        float H  = (s == 0) ? 100.f : 200.f;
        float sh = (s == 0) ? 1.f   : 2.f;
        float op = opac[g*2+s];
        bool mk = pos && (op > 0.05f);
        float u = -sh*my + 0.5f*H;
        float v = -sh*mx + 0.5f*H;
        float a  = sh*sh*c3 + 0.3f;
        float cc = sh*sh*c0 + 0.3f;
        float bb = sh*sh*c1;
        float det = fmaxf(a*cc - bb*bb, 1e-8f);
        float inv = 1.f/det;
        float ct = logf(255.f*fmaxf(op, 1e-20f));
        float rx = sqrtf(fmaxf(2.f*ct*a , 0.f));
        float ry = sqrtf(fmaxf(2.f*ct*cc, 0.f));
        if (!mk) rx = -1.f;
        g_p0[s][g] = make_float4(u, v, rx, ry);
        g_p1[s][g] = make_float4(cc*inv, -bb*inv, a*inv, op);
    }
}

__global__ void numg_k(const float* __restrict__ means, const float* __restrict__ opac,
                       float* __restrict__ out, int out_size)
{
    __shared__ int red[256];
    int tid = threadIdx.x;
    int cnt = 0;
    for (int g = tid; g < G_TOT; g += 256) {
        float mx = means[g*3], my = means[g*3+1], mz = means[g*3+2];
        bool pos = (mx >= -50.f) && (mx <= 50.f) && (my >= -50.f) && (my <= 50.f)
                && (mz >= -4.f) && (mz <= 4.f);
        if (pos) {
            if (opac[g*2+0] > 0.05f) cnt++;
            if (opac[g*2+1] > 0.05f) cnt++;
        }
    }
    red[tid] = cnt; __syncthreads();
    for (int st = 128; st > 0; st >>= 1) {
        if (tid < st) red[tid] += red[tid+st];
        __syncthreads();
    }
    if (tid == 0 && out_size > 64*200*200) out[64*200*200] = (float)red[0];
}

// ---------------- weight prep: [l][tap][ci][co] + tf32 hi/lo split ----------------
__global__ void prep_w(const float* __restrict__ conv1w, const float* __restrict__ blkw,
                       const float* __restrict__ upw)
{
    int idx = blockIdx.x * 256 + threadIdx.x;
    if (idx >= 11*9*64*64) return;
    int co = idx & 63;
    int t  = idx >> 6;
    int ci = t & 63; t >>= 6;
    int tap = t % 9;
    int l = t / 9;
    const float* src;
    if (l == 0)      src = conv1w;
    else if (l <= 4) src = blkw + (l-1)*36864;
    else if (l == 5) src = conv1w + 36864;
    else if (l == 6) src = upw;
    else             src = blkw + (l-3)*36864;
    float w = src[co*576 + ci*9 + tap];
    unsigned h = t32(w);
    float hf = __uint_as_float(h);
    g_wh[idx] = hf;
    g_wl[idx] = __uint_as_float(t32(w - hf));
}

// ---------------- tiled ordered splatting -> padded NHWC ----------------
__global__ void render_k(int s, const float* __restrict__ feats,
                         float* __restrict__ out, int H)
{
    const int W = H;
    __shared__ int s_list[G_TOT];
    __shared__ int s_wcnt[8];
    int tid = threadIdx.x;
    int lane = tid & 31, wid = tid >> 5;
    int tx0 = blockIdx.x * 16, ty0 = blockIdx.y * 16;
    float xmin = (float)tx0, xmax = (float)min(tx0 + 15, W - 1);
    float ymin = (float)ty0, ymax = (float)min(ty0 + 15, H - 1);

    int num = 0;
    for (int base = 0; base < G_TOT; base += 256) {
        int g = base + tid;
        float4 q = g_p0[s][g];
        bool ok = (q.z >= 0.f) &&
                  (q.x + q.z >= xmin) && (q.x - q.z <= xmax) &&
                  (q.y + q.w >= ymin) && (q.y - q.w <= ymax);
        unsigned m = __ballot_sync(0xffffffffu, ok);
        if (lane == 0) s_wcnt[wid] = __popc(m);
        __syncthreads();
        int off = num + __popc(m & ((1u << lane) - 1u));
        int tot = 0;
        #pragma unroll
        for (int w2 = 0; w2 < 8; w2++) {
            int c = s_wcnt[w2];
            if (w2 < wid) off += c;
            tot += c;
        }
        if (ok) s_list[off] = g;
        num += tot;
        __syncthreads();
    }

    int px = tx0 + (tid & 15);
    int py = ty0 + (tid >> 4);
    float fx = (float)px, fy = (float)py;
    float T = 1.f;
    float acc[64];
    #pragma unroll
    for (int d = 0; d < 64; d++) acc[d] = 0.f;

    for (int i = 0; i < num; i++) {
        int g = s_list[i];
        float4 q = g_p0[s][g];
        float4 r = g_p1[s][g];
        float dx = q.x - fx, dy = q.y - fy;
        float power = -0.5f*(r.x*dx*dx + r.z*dy*dy) - r.y*dx*dy;
        float alpha = fminf(r.w * expf(power), 0.99f);
        if (alpha >= (1.f/255.f) && power <= 0.f) {
            float wg = alpha * T;
            T *= (1.f - alpha);
            const float4* f4 = (const float4*)(feats + (size_t)g * 64);
            #pragma unroll
            for (int j = 0; j < 16; j++) {
                float4 fv = __ldg(f4 + j);
                acc[4*j+0] += wg*fv.x;
                acc[4*j+1] += wg*fv.y;
                acc[4*j+2] += wg*fv.z;
                acc[4*j+3] += wg*fv.w;
            }
        }
    }
    if (px < W && py < H) {
        float4* o = (float4*)(out + (((size_t)(py+1))*(W+2) + (px+1))*64);
        #pragma unroll
        for (int j = 0; j < 16; j++)
            o[j] = make_float4(acc[4*j], acc[4*j+1], acc[4*j+2], acc[4*j+3]);
    }
}

// ---------------- conv3x3 64->64 via m16n8k8 tf32 (3xTF32) ----------------
// tile: 4 rows x 64 px x 64 co; 8 warps; padded NHWC in, NHWC/CHW out
#define SM_A 26112     // 64ci * 408 (6r*68c)
#define SM_W 4608      // 64ci * 72
#define CONV_SMEM ((SM_A + 2*SM_W)*4)

__device__ __forceinline__ void epi_store(float v0, float v1, int y, int px, int ch,
    const float* add, int add_pad, float* out, int out_chw, int relu, int H, int W)
{
    if (px >= W) return;
    if (add) {
        const float* ap = add_pad
            ? (add + (((size_t)(y+1))*(W+2) + px + 1)*64 + ch)
            : (add + ((size_t)y*W + px)*64 + ch);
        float2 t = *(const float2*)ap;
        v0 += t.x; v1 += t.y;
    }
    if (relu) { v0 = fmaxf(v0, 0.f); v1 = fmaxf(v1, 0.f); }
    if (out_chw) {
        out[(size_t)ch*H*W + (size_t)y*W + px]     = v0;
        out[(size_t)(ch+1)*H*W + (size_t)y*W + px] = v1;
    } else {
        *(float2*)(out + (((size_t)(y+1))*(W+2) + px + 1)*64 + ch) = make_float2(v0, v1);
    }
}

__global__ void __launch_bounds__(256, 1)
conv_mma(const float* __restrict__ in, int layer,
         const float* __restrict__ add, int add_pad,
         float* __restrict__ out, int out_chw, int relu,
         int H, int W)
{
    extern __shared__ float sm[];
    float* As = sm;
    float* Wh = sm + SM_A;
    float* Wl = Wh + SM_W;

    int tid = threadIdx.x;
    int lane = tid & 31, wid = tid >> 5;
    int x0 = blockIdx.x * 64;
    int y0 = blockIdx.y * 4;
    int Wp = W + 2;

    for (int i = tid; i < 16*408; i += 256) {
        int ci4 = i / 408;
        int rc  = i - ci4 * 408;
        int r = rc / 68;
        int c = rc - r * 68;
        float4 v = make_float4(0.f, 0.f, 0.f, 0.f);
        if (c < 66 && (x0 + c) < Wp)
            v = *(const float4*)(in + (((size_t)(y0 + r))*Wp + x0 + c)*64 + ci4*4);
        As[(ci4*4+0)*408 + rc] = v.x;
        As[(ci4*4+1)*408 + rc] = v.y;
        As[(ci4*4+2)*408 + rc] = v.z;
        As[(ci4*4+3)*408 + rc] = v.w;
    }

    int yl = wid >> 1;
    int xw = (wid & 1) * 32;
    int qp = lane >> 2;           // groupID 0..7
    int qk = lane & 3;            // threadID_in_group 0..3

    float cA[8][4], cB[8][4];
    #pragma unroll
    for (int n = 0; n < 8; n++)
        #pragma unroll
        for (int j = 0; j < 4; j++) { cA[n][j] = 0.f; cB[n][j] = 0.f; }

    const float* whg = g_wh + (size_t)layer * 9 * 4096;
    const float* wlg = g_wl + (size_t)layer * 9 * 4096;

    #pragma unroll 1
    for (int tap = 0; tap < 9; tap++) {
        __syncthreads();
        const float* whp = whg + tap*4096;
        const float* wlp = wlg + tap*4096;
        for (int i = tid; i < 1024; i += 256) {
            int co4 = i & 15;
            int ci  = i >> 4;
            float4 vh = *(const float4*)(whp + ci*64 + co4*4);
            float4 vl = *(const float4*)(wlp + ci*64 + co4*4);
            *(float4*)&Wh[ci*72 + co4*4] = vh;
            *(float4*)&Wl[ci*72 + co4*4] = vl;
        }
        __syncthreads();

        int dy = tap / 3;
        int dx = tap - 3*dy;
        int abase = qk*408 + (yl + dy)*68 + xw + dx + qp;

        #pragma unroll
        for (int kst = 0; kst < 8; kst++) {
            int ab = abase + kst*3264;
            // frag A (px xw+qp, xw+qp+8): a0=(g,t) a1=(g+8,t) a2=(g,t+4) a3=(g+8,t+4)
            float f0 = As[ab],        f1 = As[ab+8];
            float f2 = As[ab+1632],   f3 = As[ab+1640];
            // frag B (px xw+16+qp, xw+24+qp)
            float g0 = As[ab+16],     g1 = As[ab+24];
            float g2 = As[ab+1648],   g3 = As[ab+1656];

            unsigned ah0=t32(f0), ah1=t32(f1), ah2=t32(f2), ah3=t32(f3);
            unsigned al0=t32(f0-__uint_as_float(ah0)), al1=t32(f1-__uint_as_float(ah1));
            unsigned al2=t32(f2-__uint_as_float(ah2)), al3=t32(f3-__uint_as_float(ah3));
            unsigned bh0=t32(g0), bh1=t32(g1), bh2=t32(g2), bh3=t32(g3);
            unsigned bl0=t32(g0-__uint_as_float(bh0)), bl1=t32(g1-__uint_as_float(bh1));
            unsigned bl2=t32(g2-__uint_as_float(bh2)), bl3=t32(g3-__uint_as_float(bh3));

            int bb = (kst*8 + qk)*72 + qp;
            #pragma unroll
            for (int n = 0; n < 8; n++) {
                unsigned wb0 = __float_as_uint(Wh[bb + n*8]);
                unsigned wb1 = __float_as_uint(Wh[bb + 288 + n*8]);
                unsigned wc0 = __float_as_uint(Wl[bb + n*8]);
                unsigned wc1 = __float_as_uint(Wl[bb + 288 + n*8]);
                MMA_TF32(cA[n][0],cA[n][1],cA[n][2],cA[n][3], ah0,ah1,ah2,ah3, wb0,wb1);
                MMA_TF32(cB[n][0],cB[n][1],cB[n][2],cB[n][3], bh0,bh1,bh2,bh3, wb0,wb1);
                MMA_TF32(cA[n][0],cA[n][1],cA[n][2],cA[n][3], al0,al1,al2,al3, wb0,wb1);
                MMA_TF32(cB[n][0],cB[n][1],cB[n][2],cB[n][3], bl0,bl1,bl2,bl3, wb0,wb1);
                MMA_TF32(cA[n][0],cA[n][1],cA[n][2],cA[n][3], ah0,ah1,ah2,ah3, wc0,wc1);
                MMA_TF32(cB[n][0],cB[n][1],cB[n][2],cB[n][3], bh0,bh1,bh2,bh3, wc0,wc1);
            }
        }
    }

    int y = y0 + yl;
    #pragma unroll
    for (int n = 0; n < 8; n++) {
        int ch = n*8 + 2*qk;
        epi_store(cA[n][0], cA[n][1], y, x0+xw+qp,    ch, add, add_pad, out, out_chw, relu, H, W);
        epi_store(cA[n][2], cA[n][3], y, x0+xw+qp+8,  ch, add, add_pad, out, out_chw, relu, H, W);
        epi_store(cB[n][0], cB[n][1], y, x0+xw+16+qp, ch, add, add_pad, out, out_chw, relu, H, W);
        epi_store(cB[n][2], cB[n][3], y, x0+xw+24+qp, ch, add, add_pad, out, out_chw, relu, H, W);
    }
}

// ---------------- bilinear 2x upsample, padded NHWC 102 -> 202 ----------------
__global__ void upsample_k(const float* __restrict__ in, float* __restrict__ out)
{
    int idx = blockIdx.x * 256 + threadIdx.x;
    if (idx >= 200*200*16) return;
    int ci4 = idx & 15;
    int p = idx >> 4;
    int x = p % 200, y = p / 200;
    float sx = 0.5f*x - 0.25f;
    float sy = 0.5f*y - 0.25f;
    float fx = floorf(sx), fy = floorf(sy);
    float tx = sx - fx, ty = sy - fy;
    int x0c = max((int)fx, 0), x1c = min((int)fx + 1, 99);
    int y0c = max((int)fy, 0), y1c = min((int)fy + 1, 99);
    float4 v00 = ((const float4*)(in + (((size_t)(y0c+1))*102 + x0c+1)*64))[ci4];
    float4 v01 = ((const float4*)(in + (((size_t)(y0c+1))*102 + x1c+1)*64))[ci4];
    float4 v10 = ((const float4*)(in + (((size_t)(y1c+1))*102 + x0c+1)*64))[ci4];
    float4 v11 = ((const float4*)(in + (((size_t)(y1c+1))*102 + x1c+1)*64))[ci4];
    float w00 = (1.f-ty)*(1.f-tx), w01 = (1.f-ty)*tx, w10 = ty*(1.f-tx), w11 = ty*tx;
    float4 r;
    r.x = w00*v00.x + w01*v01.x + w10*v10.x + w11*v11.x;
    r.y = w00*v00.y + w01*v01.y + w10*v10.y + w11*v11.y;
    r.z = w00*v00.z + w01*v01.z + w10*v10.z + w11*v11.z;
    r.w = w00*v00.w + w01*v01.w + w10*v10.w + w11*v11.w;
    ((float4*)(out + (((size_t)(y+1))*202 + x+1)*64))[ci4] = r;
}

// ---------------- instance norm (deterministic two-stage) ----------------
__global__ void in_rows_k(const float* __restrict__ x)
{
    int r = blockIdx.x;
    int c = threadIdx.x;
    const float* p = x + (size_t)r * 202 * 64;
    float s = 0.f, s2 = 0.f;
    for (int px = 0; px < 202; px++) {
        float v = p[px*64 + c];
        s += v; s2 += v*v;
    }
    g_part[r*128 + c]      = s;
    g_part[r*128 + 64 + c] = s2;
}

__global__ void in_stats_k()
{
    int c = threadIdx.x;
    float s = 0.f, s2 = 0.f;
    for (int r = 0; r < 202; r++) {
        s  += g_part[r*128 + c];
        s2 += g_part[r*128 + 64 + c];
    }
    float mu  = s * (1.f/40000.f);
    float var = s2 * (1.f/40000.f) - mu*mu;
    g_stats[c*2]   = mu;
    g_stats[c*2+1] = 1.f/sqrtf(var + 1e-5f);
}

__global__ void in_apply_k(const float* __restrict__ t, const float* __restrict__ addp,
                           float* __restrict__ out)
{
    int idx = blockIdx.x * 256 + threadIdx.x;
    if (idx >= 200*200*64) return;
    int ch = idx & 63;
    int p = idx >> 6;
    int x = p % 200, y = p / 200;
    size_t o = (((size_t)(y+1))*202 + x+1)*64 + ch;
    out[o] = (t[o] - g_stats[ch*2]) * g_stats[ch*2+1] + addp[o];
}

// ---------------- launch ----------------
extern "C" void kernel_launch(void* const* d_in, const int* in_sizes, int n_in,
                              void* d_out, int out_size)
{
    const float* features = (const float*)d_in[0];
    const float* means    = (const float*)d_in[1];
    const float* cov      = (const float*)d_in[2];
    const float* opac     = (const float*)d_in[3];
    const float* emb      = (const float*)d_in[4];
    const float* conv1w   = (const float*)d_in[5];
    const float* blkw     = (const float*)d_in[6];
    const float* upw      = (const float*)d_in[7];
    float* out = (float*)d_out;

    cudaFuncSetAttribute(conv_mma, cudaFuncAttributeMaxDynamicSharedMemorySize, CONV_SMEM);

    float *s0a,*s0b,*s0c,*s0d,*b1,*b2,*b3,*b4;
    cudaGetSymbolAddress((void**)&s0a, g_s0a);
    cudaGetSymbolAddress((void**)&s0b, g_s0b);
    cudaGetSymbolAddress((void**)&s0c, g_s0c);
    cudaGetSymbolAddress((void**)&s0d, g_s0d);
    cudaGetSymbolAddress((void**)&b1,  g_b1);
    cudaGetSymbolAddress((void**)&b2,  g_b2);
    cudaGetSymbolAddress((void**)&b3,  g_b3);
    cudaGetSymbolAddress((void**)&b4,  g_b4);

    prep_k<<<8, 256>>>(means, cov, opac);
    numg_k<<<1, 256>>>(means, opac, out, out_size);
    prep_w<<<1584, 256>>>(conv1w, blkw, upw);
    render_k<<<dim3(7,7),   256>>>(0, features, s0a, 100);
    render_k<<<dim3(13,13), 256>>>(1, features, b1, 200);

    dim3 cb(256);
    dim3 gs0(2, 25);
    dim3 gs1(4, 50);

    // stage 0 @100x100 (layers 0..4)
    conv_mma<<<gs0, cb, CONV_SMEM>>>(s0a, 0, emb, 0, s0b, 0, 0, 100, 100);
    conv_mma<<<gs0, cb, CONV_SMEM>>>(s0b, 1, nullptr, 1, s0c, 0, 1, 100, 100);
    conv_mma<<<gs0, cb, CONV_SMEM>>>(s0c, 2, s0b, 1, s0d, 0, 1, 100, 100);
    conv_mma<<<gs0, cb, CONV_SMEM>>>(s0d, 3, nullptr, 1, s0b, 0, 1, 100, 100);
    conv_mma<<<gs0, cb, CONV_SMEM>>>(s0b, 4, s0d, 1, s0c, 0, 1, 100, 100);

    // stage 1 @200x200 (layers 5..10)
    conv_mma<<<gs1, cb, CONV_SMEM>>>(b1, 5, nullptr, 1, b2, 0, 0, 200, 200);
    upsample_k<<<2500, 256>>>(s0c, b3);
    conv_mma<<<gs1, cb, CONV_SMEM>>>(b3, 6, nullptr, 1, b4, 0, 0, 200, 200);
    in_rows_k<<<202, 64>>>(b4);
    in_stats_k<<<1, 64>>>();
    in_apply_k<<<10000, 256>>>(b4, b2, b1);
    conv_mma<<<gs1, cb, CONV_SMEM>>>(b1, 7, nullptr, 1, b3, 0, 1, 200, 200);
    conv_mma<<<gs1, cb, CONV_SMEM>>>(b3, 8, b1, 1, b4, 0, 1, 200, 200);
    conv_mma<<<gs1, cb, CONV_SMEM>>>(b4, 9, nullptr, 1, b3, 0, 1, 200, 200);
    conv_mma<<<gs1, cb, CONV_SMEM>>>(b3, 10, b4, 1, out, 1, 1, 200, 200);
}

// round 8
// speedup vs baseline: 2.9803x; 1.6169x over previous
#include <cuda_runtime.h>
#include <cuda_bf16.h>
#include <math.h>

#define G_TOT 2048

// ---------------- scratch (zero-initialized globals; halos never written) ----------------
__device__ __align__(128) float4 g_p0[2][G_TOT];
__device__ __align__(128) float4 g_p1[2][G_TOT];
__device__ __align__(128) float g_s0a[102*102*64];
__device__ __align__(128) float g_s0b[102*102*64];
__device__ __align__(128) float g_s0c[102*102*64];
__device__ __align__(128) float g_s0d[102*102*64];
__device__ __align__(128) float g_b1[202*202*64];
__device__ __align__(128) float g_b2[202*202*64];
__device__ __align__(128) float g_b3[202*202*64];
__device__ __align__(128) float g_b4[202*202*64];
__device__ __align__(128) unsigned g_wph[11*9*32*64];   // bf16x2 (ci-pair) hi
__device__ __align__(128) unsigned g_wpl[11*9*32*64];   // bf16x2 (ci-pair) lo
__device__ __align__(128) float g_part[202*128];
__device__ float g_stats[128];

#define MMA_BF16(c0,c1,c2,c3,a0,a1,a2,a3,b0,b1) \
  asm("mma.sync.aligned.m16n8k16.row.col.f32.bf16.bf16.f32 " \
      "{%0,%1,%2,%3}, {%4,%5,%6,%7}, {%8,%9}, {%0,%1,%2,%3};" \
      : "+f"(c0),"+f"(c1),"+f"(c2),"+f"(c3) \
      : "r"(a0),"r"(a1),"r"(a2),"r"(a3),"r"(b0),"r"(b1))

// ---------------- gaussian preprocessing ----------------
__global__ void prep_k(const float* __restrict__ means, const float* __restrict__ cov,
                       const float* __restrict__ opac)
{
    int g = blockIdx.x * blockDim.x + threadIdx.x;
    if (g >= G_TOT) return;
    float mx = means[g*3+0], my = means[g*3+1], mz = means[g*3+2];
    bool pos = (mx >= -50.f) && (mx <= 50.f) && (my >= -50.f) && (my <= 50.f)
            && (mz >= -4.f)  && (mz <= 4.f);
    float c0 = cov[g*6+0], c1 = cov[g*6+1], c3 = cov[g*6+3];
    #pragma unroll
    for (int s = 0; s < 2; s++) {
        float H  = (s == 0) ? 100.f : 200.f;
        float sh = (s == 0) ? 1.f   : 2.f;
        float op = opac[g*2+s];
        bool mk = pos && (op > 0.05f);
        float u = -sh*my + 0.5f*H;
        float v = -sh*mx + 0.5f*H;
        float a  = sh*sh*c3 + 0.3f;
        float cc = sh*sh*c0 + 0.3f;
        float bb = sh*sh*c1;
        float det = fmaxf(a*cc - bb*bb, 1e-8f);
        float inv = 1.f/det;
        float ct = logf(255.f*fmaxf(op, 1e-20f));
        float rx = sqrtf(fmaxf(2.f*ct*a , 0.f));
        float ry = sqrtf(fmaxf(2.f*ct*cc, 0.f));
        if (!mk) rx = -1.f;
        g_p0[s][g] = make_float4(u, v, rx, ry);
        g_p1[s][g] = make_float4(cc*inv, -bb*inv, a*inv, op);
    }
}

__global__ void numg_k(const float* __restrict__ means, const float* __restrict__ opac,
                       float* __restrict__ out, int out_size)
{
    __shared__ int red[256];
    int tid = threadIdx.x;
    int cnt = 0;
    for (int g = tid; g < G_TOT; g += 256) {
        float mx = means[g*3], my = means[g*3+1], mz = means[g*3+2];
        bool pos = (mx >= -50.f) && (mx <= 50.f) && (my >= -50.f) && (my <= 50.f)
                && (mz >= -4.f) && (mz <= 4.f);
        if (pos) {
            if (opac[g*2+0] > 0.05f) cnt++;
            if (opac[g*2+1] > 0.05f) cnt++;
        }
    }
    red[tid] = cnt; __syncthreads();
    for (int st = 128; st > 0; st >>= 1) {
        if (tid < st) red[tid] += red[tid+st];
        __syncthreads();
    }
    if (tid == 0 && out_size > 64*200*200) out[64*200*200] = (float)red[0];
}

// ---------------- weight prep: [l][tap][ci-pair][co], bf16 hi/lo split ----------------
__global__ void prep_w(const float* __restrict__ conv1w, const float* __restrict__ blkw,
                       const float* __restrict__ upw)
{
    int idx = blockIdx.x * 256 + threadIdx.x;
    if (idx >= 11*9*32*64) return;
    int co   = idx & 63;
    int pair = (idx >> 6) & 31;
    int t    = idx >> 11;
    int tap  = t % 9;
    int l    = t / 9;
    const float* src;
    if (l == 0)      src = conv1w;
    else if (l <= 4) src = blkw + (l-1)*36864;
    else if (l == 5) src = conv1w + 36864;
    else if (l == 6) src = upw;
    else             src = blkw + (l-3)*36864;
    float w0 = src[co*576 + (2*pair  )*9 + tap];
    float w1 = src[co*576 + (2*pair+1)*9 + tap];
    __nv_bfloat162 h = __floats2bfloat162_rn(w0, w1);
    float r0 = w0 - __bfloat162float(h.x);
    float r1 = w1 - __bfloat162float(h.y);
    __nv_bfloat162 lo = __floats2bfloat162_rn(r0, r1);
    g_wph[idx] = *reinterpret_cast<unsigned*>(&h);
    g_wpl[idx] = *reinterpret_cast<unsigned*>(&lo);
}

// ---------------- tiled ordered splatting -> padded NHWC ----------------
__global__ void render_k(int s, const float* __restrict__ feats,
                         float* __restrict__ out, int H)
{
    const int W = H;
    __shared__ int s_list[G_TOT];
    __shared__ int s_wcnt[8];
    int tid = threadIdx.x;
    int lane = tid & 31, wid = tid >> 5;
    int tx0 = blockIdx.x * 16, ty0 = blockIdx.y * 16;
    float xmin = (float)tx0, xmax = (float)min(tx0 + 15, W - 1);
    float ymin = (float)ty0, ymax = (float)min(ty0 + 15, H - 1);

    int num = 0;
    for (int base = 0; base < G_TOT; base += 256) {
        int g = base + tid;
        float4 q = g_p0[s][g];
        bool ok = (q.z >= 0.f) &&
                  (q.x + q.z >= xmin) && (q.x - q.z <= xmax) &&
                  (q.y + q.w >= ymin) && (q.y - q.w <= ymax);
        unsigned m = __ballot_sync(0xffffffffu, ok);
        if (lane == 0) s_wcnt[wid] = __popc(m);
        __syncthreads();
        int off = num + __popc(m & ((1u << lane) - 1u));
        int tot = 0;
        #pragma unroll
        for (int w2 = 0; w2 < 8; w2++) {
            int c = s_wcnt[w2];
            if (w2 < wid) off += c;
            tot += c;
        }
        if (ok) s_list[off] = g;
        num += tot;
        __syncthreads();
    }

    int px = tx0 + (tid & 15);
    int py = ty0 + (tid >> 4);
    float fx = (float)px, fy = (float)py;
    float T = 1.f;
    float acc[64];
    #pragma unroll
    for (int d = 0; d < 64; d++) acc[d] = 0.f;

    for (int i = 0; i < num; i++) {
        int g = s_list[i];
        float4 q = g_p0[s][g];
        float4 r = g_p1[s][g];
        float dx = q.x - fx, dy = q.y - fy;
        float power = -0.5f*(r.x*dx*dx + r.z*dy*dy) - r.y*dx*dy;
        float alpha = fminf(r.w * expf(power), 0.99f);
        if (alpha >= (1.f/255.f) && power <= 0.f) {
            float wg = alpha * T;
            T *= (1.f - alpha);
            const float4* f4 = (const float4*)(feats + (size_t)g * 64);
            #pragma unroll
            for (int j = 0; j < 16; j++) {
                float4 fv = __ldg(f4 + j);
                acc[4*j+0] += wg*fv.x;
                acc[4*j+1] += wg*fv.y;
                acc[4*j+2] += wg*fv.z;
                acc[4*j+3] += wg*fv.w;
            }
        }
    }
    if (px < W && py < H) {
        float4* o = (float4*)(out + (((size_t)(py+1))*(W+2) + (px+1))*64);
        #pragma unroll
        for (int j = 0; j < 16; j++)
            o[j] = make_float4(acc[4*j], acc[4*j+1], acc[4*j+2], acc[4*j+3]);
    }
}

// ---------------- conv3x3 64->64 via m16n8k16 bf16 (hi/lo split) ----------------
// tile: 4 rows x 64 px x 64 co; 8 warps; padded NHWC in, NHWC/CHW out
// smem (u32 units): Ah[32pair][408], Al[32pair][408], Wh2[32pair][72], Wl2[32pair][72]
#define SM_A 13056     // 32*408 per array
#define SM_W 2304      // 32*72 per array
#define CONV_SMEM ((2*SM_A + 2*SM_W)*4)

__device__ __forceinline__ void epi_store(float v0, float v1, int y, int px, int ch,
    const float* add, int add_pad, float* out, int out_chw, int relu, int H, int W)
{
    if (px >= W) return;
    if (add) {
        const float* ap = add_pad
            ? (add + (((size_t)(y+1))*(W+2) + px + 1)*64 + ch)
            : (add + ((size_t)y*W + px)*64 + ch);
        float2 t = *(const float2*)ap;
        v0 += t.x; v1 += t.y;
    }
    if (relu) { v0 = fmaxf(v0, 0.f); v1 = fmaxf(v1, 0.f); }
    if (out_chw) {
        out[(size_t)ch*H*W + (size_t)y*W + px]     = v0;
        out[(size_t)(ch+1)*H*W + (size_t)y*W + px] = v1;
    } else {
        *(float2*)(out + (((size_t)(y+1))*(W+2) + px + 1)*64 + ch) = make_float2(v0, v1);
    }
}

__global__ void __launch_bounds__(256, 1)
conv_mma(const float* __restrict__ in, int layer,
         const float* __restrict__ add, int add_pad,
         float* __restrict__ out, int out_chw, int relu,
         int H, int W)
{
    extern __shared__ unsigned smu[];
    unsigned* Ah  = smu;
    unsigned* Al  = smu + SM_A;
    unsigned* Wh2 = smu + 2*SM_A;
    unsigned* Wl2 = Wh2 + SM_W;

    int tid = threadIdx.x;
    int lane = tid & 31, wid = tid >> 5;
    int x0 = blockIdx.x * 64;
    int y0 = blockIdx.y * 4;
    int Wp = W + 2;

    // stage A: fp32 -> bf16 hi/lo, ci-pair packed; pairs 2m,2m+1 from float4 ci 4m..4m+3
    for (int i = tid; i < 16*408; i += 256) {
        int m  = i / 408;
        int rc = i - m * 408;
        int r = rc / 68;
        int c = rc - r * 68;
        float4 v = make_float4(0.f, 0.f, 0.f, 0.f);
        if (c < 66 && (x0 + c) < Wp)
            v = *(const float4*)(in + (((size_t)(y0 + r))*Wp + x0 + c)*64 + m*4);
        __nv_bfloat162 h0 = __floats2bfloat162_rn(v.x, v.y);
        __nv_bfloat162 h1 = __floats2bfloat162_rn(v.z, v.w);
        __nv_bfloat162 l0 = __floats2bfloat162_rn(v.x - __bfloat162float(h0.x),
                                                  v.y - __bfloat162float(h0.y));
        __nv_bfloat162 l1 = __floats2bfloat162_rn(v.z - __bfloat162float(h1.x),
                                                  v.w - __bfloat162float(h1.y));
        Ah[(2*m  )*408 + rc] = *reinterpret_cast<unsigned*>(&h0);
        Ah[(2*m+1)*408 + rc] = *reinterpret_cast<unsigned*>(&h1);
        Al[(2*m  )*408 + rc] = *reinterpret_cast<unsigned*>(&l0);
        Al[(2*m+1)*408 + rc] = *reinterpret_cast<unsigned*>(&l1);
    }

    int yl = wid >> 1;            // warp row 0..3
    int xw = (wid & 1) * 32;      // warp x base
    int qp = lane >> 2;           // group 0..7
    int qk = lane & 3;            // in-group 0..3

    float cA[8][4], cB[8][4];
    #pragma unroll
    for (int n = 0; n < 8; n++)
        #pragma unroll
        for (int j = 0; j < 4; j++) { cA[n][j] = 0.f; cB[n][j] = 0.f; }

    #pragma unroll 1
    for (int tap = 0; tap < 9; tap++) {
        __syncthreads();
        const uint4* ph = (const uint4*)(g_wph + ((size_t)layer*9 + tap)*2048);
        const uint4* pl = (const uint4*)(g_wpl + ((size_t)layer*9 + tap)*2048);
        for (int i = tid; i < 512; i += 256) {
            uint4 vh = ph[i], vl = pl[i];
            int pair = i >> 4, co4 = (i & 15) * 4;
            *(uint4*)&Wh2[pair*72 + co4] = vh;
            *(uint4*)&Wl2[pair*72 + co4] = vl;
        }
        __syncthreads();

        int dy = tap / 3;
        int dx = tap - 3*dy;
        int abase = (yl + dy)*68 + xw + dx + qp;

        #pragma unroll
        for (int kst = 0; kst < 4; kst++) {
            int p0 = kst*8 + qk;
            int p1 = p0 + 4;
            int a0b = p0*408 + abase, a1b = p1*408 + abase;
            // m-frag A (px xw+qp, xw+qp+8)
            unsigned ah0 = Ah[a0b],     ah1 = Ah[a0b+8];
            unsigned ah2 = Ah[a1b],     ah3 = Ah[a1b+8];
            unsigned al0 = Al[a0b],     al1 = Al[a0b+8];
            unsigned al2 = Al[a1b],     al3 = Al[a1b+8];
            // m-frag B (px xw+16+qp, xw+24+qp)
            unsigned bh0 = Ah[a0b+16],  bh1 = Ah[a0b+24];
            unsigned bh2 = Ah[a1b+16],  bh3 = Ah[a1b+24];
            unsigned bl0 = Al[a0b+16],  bl1 = Al[a0b+24];
            unsigned bl2 = Al[a1b+16],  bl3 = Al[a1b+24];

            int wb0 = p0*72 + qp;
            int wb1 = p1*72 + qp;
            #pragma unroll
            for (int n = 0; n < 8; n++) {
                unsigned w0 = Wh2[wb0 + n*8];
                unsigned w1 = Wh2[wb1 + n*8];
                unsigned v0 = Wl2[wb0 + n*8];
                unsigned v1 = Wl2[wb1 + n*8];
                MMA_BF16(cA[n][0],cA[n][1],cA[n][2],cA[n][3], ah0,ah1,ah2,ah3, w0,w1);
                MMA_BF16(cB[n][0],cB[n][1],cB[n][2],cB[n][3], bh0,bh1,bh2,bh3, w0,w1);
                MMA_BF16(cA[n][0],cA[n][1],cA[n][2],cA[n][3], al0,al1,al2,al3, w0,w1);
                MMA_BF16(cB[n][0],cB[n][1],cB[n][2],cB[n][3], bl0,bl1,bl2,bl3, w0,w1);
                MMA_BF16(cA[n][0],cA[n][1],cA[n][2],cA[n][3], ah0,ah1,ah2,ah3, v0,v1);
                MMA_BF16(cB[n][0],cB[n][1],cB[n][2],cB[n][3], bh0,bh1,bh2,bh3, v0,v1);
            }
        }
    }

    // epilogue: c0,c1 = (px g, co 2qk/2qk+1); c2,c3 = (px g+8, ...)
    int y = y0 + yl;
    #pragma unroll
    for (int n = 0; n < 8; n++) {
        int ch = n*8 + 2*qk;
        epi_store(cA[n][0], cA[n][1], y, x0+xw+qp,    ch, add, add_pad, out, out_chw, relu, H, W);
        epi_store(cA[n][2], cA[n][3], y, x0+xw+qp+8,  ch, add, add_pad, out, out_chw, relu, H, W);
        epi_store(cB[n][0], cB[n][1], y, x0+xw+16+qp, ch, add, add_pad, out, out_chw, relu, H, W);
        epi_store(cB[n][2], cB[n][3], y, x0+xw+24+qp, ch, add, add_pad, out, out_chw, relu, H, W);
    }
}

// ---------------- bilinear 2x upsample, padded NHWC 102 -> 202 ----------------
__global__ void upsample_k(const float* __restrict__ in, float* __restrict__ out)
{
    int idx = blockIdx.x * 256 + threadIdx.x;
    if (idx >= 200*200*16) return;
    int ci4 = idx & 15;
    int p = idx >> 4;
    int x = p % 200, y = p / 200;
    float sx = 0.5f*x - 0.25f;
    float sy = 0.5f*y - 0.25f;
    float fx = floorf(sx), fy = floorf(sy);
    float tx = sx - fx, ty = sy - fy;
    int x0c = max((int)fx, 0), x1c = min((int)fx + 1, 99);
    int y0c = max((int)fy, 0), y1c = min((int)fy + 1, 99);
    float4 v00 = ((const float4*)(in + (((size_t)(y0c+1))*102 + x0c+1)*64))[ci4];
    float4 v01 = ((const float4*)(in + (((size_t)(y0c+1))*102 + x1c+1)*64))[ci4];
    float4 v10 = ((const float4*)(in + (((size_t)(y1c+1))*102 + x0c+1)*64))[ci4];
    float4 v11 = ((const float4*)(in + (((size_t)(y1c+1))*102 + x1c+1)*64))[ci4];
    float w00 = (1.f-ty)*(1.f-tx), w01 = (1.f-ty)*tx, w10 = ty*(1.f-tx), w11 = ty*tx;
    float4 r;
    r.x = w00*v00.x + w01*v01.x + w10*v10.x + w11*v11.x;
    r.y = w00*v00.y + w01*v01.y + w10*v10.y + w11*v11.y;
    r.z = w00*v00.z + w01*v01.z + w10*v10.z + w11*v11.z;
    r.w = w00*v00.w + w01*v01.w + w10*v10.w + w11*v11.w;
    ((float4*)(out + (((size_t)(y+1))*202 + x+1)*64))[ci4] = r;
}

// ---------------- instance norm (deterministic two-stage) ----------------
__global__ void in_rows_k(const float* __restrict__ x)
{
    int r = blockIdx.x;
    int c = threadIdx.x;
    const float* p = x + (size_t)r * 202 * 64;
    float s = 0.f, s2 = 0.f;
    for (int px = 0; px < 202; px++) {
        float v = p[px*64 + c];
        s += v; s2 += v*v;
    }
    g_part[r*128 + c]      = s;
    g_part[r*128 + 64 + c] = s2;
}

__global__ void in_stats_k()
{
    int c = threadIdx.x;
    float s = 0.f, s2 = 0.f;
    for (int r = 0; r < 202; r++) {
        s  += g_part[r*128 + c];
        s2 += g_part[r*128 + 64 + c];
    }
    float mu  = s * (1.f/40000.f);
    float var = s2 * (1.f/40000.f) - mu*mu;
    g_stats[c*2]   = mu;
    g_stats[c*2+1] = 1.f/sqrtf(var + 1e-5f);
}

__global__ void in_apply_k(const float* __restrict__ t, const float* __restrict__ addp,
                           float* __restrict__ out)
{
    int idx = blockIdx.x * 256 + threadIdx.x;
    if (idx >= 200*200*64) return;
    int ch = idx & 63;
    int p = idx >> 6;
    int x = p % 200, y = p / 200;
    size_t o = (((size_t)(y+1))*202 + x+1)*64 + ch;
    out[o] = (t[o] - g_stats[ch*2]) * g_stats[ch*2+1] + addp[o];
}

// ---------------- launch ----------------
extern "C" void kernel_launch(void* const* d_in, const int* in_sizes, int n_in,
                              void* d_out, int out_size)
{
    const float* features = (const float*)d_in[0];
    const float* means    = (const float*)d_in[1];
    const float* cov      = (const float*)d_in[2];
    const float* opac     = (const float*)d_in[3];
    const float* emb      = (const float*)d_in[4];
    const float* conv1w   = (const float*)d_in[5];
    const float* blkw     = (const float*)d_in[6];
    const float* upw      = (const float*)d_in[7];
    float* out = (float*)d_out;

    cudaFuncSetAttribute(conv_mma, cudaFuncAttributeMaxDynamicSharedMemorySize, CONV_SMEM);

    float *s0a,*s0b,*s0c,*s0d,*b1,*b2,*b3,*b4;
    cudaGetSymbolAddress((void**)&s0a, g_s0a);
    cudaGetSymbolAddress((void**)&s0b, g_s0b);
    cudaGetSymbolAddress((void**)&s0c, g_s0c);
    cudaGetSymbolAddress((void**)&s0d, g_s0d);
    cudaGetSymbolAddress((void**)&b1,  g_b1);
    cudaGetSymbolAddress((void**)&b2,  g_b2);
    cudaGetSymbolAddress((void**)&b3,  g_b3);
    cudaGetSymbolAddress((void**)&b4,  g_b4);

    prep_k<<<8, 256>>>(means, cov, opac);
    numg_k<<<1, 256>>>(means, opac, out, out_size);
    prep_w<<<792, 256>>>(conv1w, blkw, upw);
    render_k<<<dim3(7,7),   256>>>(0, features, s0a, 100);
    render_k<<<dim3(13,13), 256>>>(1, features, b1, 200);

    dim3 cb(256);
    dim3 gs0(2, 25);
    dim3 gs1(4, 50);

    // stage 0 @100x100 (layers 0..4)
    conv_mma<<<gs0, cb, CONV_SMEM>>>(s0a, 0, emb, 0, s0b, 0, 0, 100, 100);
    conv_mma<<<gs0, cb, CONV_SMEM>>>(s0b, 1, nullptr, 1, s0c, 0, 1, 100, 100);
    conv_mma<<<gs0, cb, CONV_SMEM>>>(s0c, 2, s0b, 1, s0d, 0, 1, 100, 100);
    conv_mma<<<gs0, cb, CONV_SMEM>>>(s0d, 3, nullptr, 1, s0b, 0, 1, 100, 100);
    conv_mma<<<gs0, cb, CONV_SMEM>>>(s0b, 4, s0d, 1, s0c, 0, 1, 100, 100);

    // stage 1 @200x200 (layers 5..10)
    conv_mma<<<gs1, cb, CONV_SMEM>>>(b1, 5, nullptr, 1, b2, 0, 0, 200, 200);
    upsample_k<<<2500, 256>>>(s0c, b3);
    conv_mma<<<gs1, cb, CONV_SMEM>>>(b3, 6, nullptr, 1, b4, 0, 0, 200, 200);
    in_rows_k<<<202, 64>>>(b4);
    in_stats_k<<<1, 64>>>();
    in_apply_k<<<10000, 256>>>(b4, b2, b1);
    conv_mma<<<gs1, cb, CONV_SMEM>>>(b1, 7, nullptr, 1, b3, 0, 1, 200, 200);
    conv_mma<<<gs1, cb, CONV_SMEM>>>(b3, 8, b1, 1, b4, 0, 1, 200, 200);
    conv_mma<<<gs1, cb, CONV_SMEM>>>(b4, 9, nullptr, 1, b3, 0, 1, 200, 200);
    conv_mma<<<gs1, cb, CONV_SMEM>>>(b3, 10, b4, 1, out, 1, 1, 200, 200);
}

// round 9
// speedup vs baseline: 3.5799x; 1.2012x over previous
#include <cuda_runtime.h>
#include <cuda_bf16.h>
#include <math.h>

#define G_TOT 2048

// ---------------- scratch (zero-initialized globals; halos never written) ----------------
__device__ __align__(128) float4 g_p0[2][G_TOT];
__device__ __align__(128) float4 g_p1[2][G_TOT];
__device__ __align__(128) float g_s0a[102*102*64];
__device__ __align__(128) float g_s0b[102*102*64];
__device__ __align__(128) float g_s0c[102*102*64];
__device__ __align__(128) float g_s0d[102*102*64];
__device__ __align__(128) float g_b1[202*202*64];
__device__ __align__(128) float g_b2[202*202*64];
__device__ __align__(128) float g_b3[202*202*64];
__device__ __align__(128) float g_b4[202*202*64];
__device__ __align__(128) unsigned g_wph[11*9*32*64];   // bf16x2 (ci-pair) hi
__device__ __align__(128) unsigned g_wpl[11*9*32*64];   // bf16x2 (ci-pair) lo
__device__ __align__(128) float g_part[202*128];
__device__ float g_stats[128];

#define MMA_BF16(c0,c1,c2,c3,a0,a1,a2,a3,b0,b1) \
  asm("mma.sync.aligned.m16n8k16.row.col.f32.bf16.bf16.f32 " \
      "{%0,%1,%2,%3}, {%4,%5,%6,%7}, {%8,%9}, {%0,%1,%2,%3};" \
      : "+f"(c0),"+f"(c1),"+f"(c2),"+f"(c3) \
      : "r"(a0),"r"(a1),"r"(a2),"r"(a3),"r"(b0),"r"(b1))

// ---------------- gaussian preprocessing ----------------
__global__ void prep_k(const float* __restrict__ means, const float* __restrict__ cov,
                       const float* __restrict__ opac)
{
    int g = blockIdx.x * blockDim.x + threadIdx.x;
    if (g >= G_TOT) return;
    float mx = means[g*3+0], my = means[g*3+1], mz = means[g*3+2];
    bool pos = (mx >= -50.f) && (mx <= 50.f) && (my >= -50.f) && (my <= 50.f)
            && (mz >= -4.f)  && (mz <= 4.f);
    float c0 = cov[g*6+0], c1 = cov[g*6+1], c3 = cov[g*6+3];
    #pragma unroll
    for (int s = 0; s < 2; s++) {
        float H  = (s == 0) ? 100.f : 200.f;
        float sh = (s == 0) ? 1.f   : 2.f;
        float op = opac[g*2+s];
        bool mk = pos && (op > 0.05f);
        float u = -sh*my + 0.5f*H;
        float v = -sh*mx + 0.5f*H;
        float a  = sh*sh*c3 + 0.3f;
        float cc = sh*sh*c0 + 0.3f;
        float bb = sh*sh*c1;
        float det = fmaxf(a*cc - bb*bb, 1e-8f);
        float inv = 1.f/det;
        float ct = logf(255.f*fmaxf(op, 1e-20f));
        float rx = sqrtf(fmaxf(2.f*ct*a , 0.f));
        float ry = sqrtf(fmaxf(2.f*ct*cc, 0.f));
        if (!mk) rx = -1.f;
        g_p0[s][g] = make_float4(u, v, rx, ry);
        g_p1[s][g] = make_float4(cc*inv, -bb*inv, a*inv, op);
    }
}

__global__ void numg_k(const float* __restrict__ means, const float* __restrict__ opac,
                       float* __restrict__ out, int out_size)
{
    __shared__ int red[256];
    int tid = threadIdx.x;
    int cnt = 0;
    for (int g = tid; g < G_TOT; g += 256) {
        float mx = means[g*3], my = means[g*3+1], mz = means[g*3+2];
        bool pos = (mx >= -50.f) && (mx <= 50.f) && (my >= -50.f) && (my <= 50.f)
                && (mz >= -4.f) && (mz <= 4.f);
        if (pos) {
            if (opac[g*2+0] > 0.05f) cnt++;
            if (opac[g*2+1] > 0.05f) cnt++;
        }
    }
    red[tid] = cnt; __syncthreads();
    for (int st = 128; st > 0; st >>= 1) {
        if (tid < st) red[tid] += red[tid+st];
        __syncthreads();
    }
    if (tid == 0 && out_size > 64*200*200) out[64*200*200] = (float)red[0];
}

// ---------------- weight prep: [l][tap][ci-pair][co], bf16 hi/lo split ----------------
__global__ void prep_w(const float* __restrict__ conv1w, const float* __restrict__ blkw,
                       const float* __restrict__ upw)
{
    int idx = blockIdx.x * 256 + threadIdx.x;
    if (idx >= 11*9*32*64) return;
    int co   = idx & 63;
    int pair = (idx >> 6) & 31;
    int t    = idx >> 11;
    int tap  = t % 9;
    int l    = t / 9;
    const float* src;
    if (l == 0)      src = conv1w;
    else if (l <= 4) src = blkw + (l-1)*36864;
    else if (l == 5) src = conv1w + 36864;
    else if (l == 6) src = upw;
    else             src = blkw + (l-3)*36864;
    float w0 = src[co*576 + (2*pair  )*9 + tap];
    float w1 = src[co*576 + (2*pair+1)*9 + tap];
    __nv_bfloat162 h = __floats2bfloat162_rn(w0, w1);
    float r0 = w0 - __bfloat162float(h.x);
    float r1 = w1 - __bfloat162float(h.y);
    __nv_bfloat162 lo = __floats2bfloat162_rn(r0, r1);
    g_wph[idx] = *reinterpret_cast<unsigned*>(&h);
    g_wpl[idx] = *reinterpret_cast<unsigned*>(&lo);
}

// ---------------- tiled ordered splatting -> padded NHWC ----------------
__global__ void render_k(int s, const float* __restrict__ feats,
                         float* __restrict__ out, int H)
{
    const int W = H;
    __shared__ int s_list[G_TOT];
    __shared__ int s_wcnt[8];
    int tid = threadIdx.x;
    int lane = tid & 31, wid = tid >> 5;
    int tx0 = blockIdx.x * 16, ty0 = blockIdx.y * 16;
    float xmin = (float)tx0, xmax = (float)min(tx0 + 15, W - 1);
    float ymin = (float)ty0, ymax = (float)min(ty0 + 15, H - 1);

    int num = 0;
    for (int base = 0; base < G_TOT; base += 256) {
        int g = base + tid;
        float4 q = g_p0[s][g];
        bool ok = (q.z >= 0.f) &&
                  (q.x + q.z >= xmin) && (q.x - q.z <= xmax) &&
                  (q.y + q.w >= ymin) && (q.y - q.w <= ymax);
        unsigned m = __ballot_sync(0xffffffffu, ok);
        if (lane == 0) s_wcnt[wid] = __popc(m);
        __syncthreads();
        int off = num + __popc(m & ((1u << lane) - 1u));
        int tot = 0;
        #pragma unroll
        for (int w2 = 0; w2 < 8; w2++) {
            int c = s_wcnt[w2];
            if (w2 < wid) off += c;
            tot += c;
        }
        if (ok) s_list[off] = g;
        num += tot;
        __syncthreads();
    }

    int px = tx0 + (tid & 15);
    int py = ty0 + (tid >> 4);
    float fx = (float)px, fy = (float)py;
    float T = 1.f;
    float acc[64];
    #pragma unroll
    for (int d = 0; d < 64; d++) acc[d] = 0.f;

    for (int i = 0; i < num; i++) {
        int g = s_list[i];
        float4 q = g_p0[s][g];
        float4 r = g_p1[s][g];
        float dx = q.x - fx, dy = q.y - fy;
        float power = -0.5f*(r.x*dx*dx + r.z*dy*dy) - r.y*dx*dy;
        float alpha = fminf(r.w * expf(power), 0.99f);
        if (alpha >= (1.f/255.f) && power <= 0.f) {
            float wg = alpha * T;
            T *= (1.f - alpha);
            const float4* f4 = (const float4*)(feats + (size_t)g * 64);
            #pragma unroll
            for (int j = 0; j < 16; j++) {
                float4 fv = __ldg(f4 + j);
                acc[4*j+0] += wg*fv.x;
                acc[4*j+1] += wg*fv.y;
                acc[4*j+2] += wg*fv.z;
                acc[4*j+3] += wg*fv.w;
            }
        }
    }
    if (px < W && py < H) {
        float4* o = (float4*)(out + (((size_t)(py+1))*(W+2) + (px+1))*64);
        #pragma unroll
        for (int j = 0; j < 16; j++)
            o[j] = make_float4(acc[4*j], acc[4*j+1], acc[4*j+2], acc[4*j+3]);
    }
}

// ---------------- conv3x3 64->64 via m16n8k16 bf16 (hi/lo split) ----------------
// templated tile: NW warps, ROWS x TW px, 64 co; padded NHWC in, NHWC/CHW out
// smem: Ah[32][AP], Al[32][AP], W double-buffer 2 x (Wh[32][72], Wl[32][72])

__device__ __forceinline__ void epi_store(float v0, float v1, int y, int px, int ch,
    const float* add, int add_pad, float* out, int out_chw, int relu, int H, int W)
{
    if (px >= W) return;
    if (add) {
        const float* ap = add_pad
            ? (add + (((size_t)(y+1))*(W+2) + px + 1)*64 + ch)
            : (add + ((size_t)y*W + px)*64 + ch);
        float2 t = *(const float2*)ap;
        v0 += t.x; v1 += t.y;
    }
    if (relu) { v0 = fmaxf(v0, 0.f); v1 = fmaxf(v1, 0.f); }
    if (out_chw) {
        out[(size_t)ch*H*W + (size_t)y*W + px]     = v0;
        out[(size_t)(ch+1)*H*W + (size_t)y*W + px] = v1;
    } else {
        *(float2*)(out + (((size_t)(y+1))*(W+2) + px + 1)*64 + ch) = make_float2(v0, v1);
    }
}

template<int NW, int ROWS, int TW>
__global__ void __launch_bounds__(NW*32, (NW==8) ? 2 : 1)
conv_mma_t(const float* __restrict__ in, int layer,
           const float* __restrict__ add, int add_pad,
           float* __restrict__ out, int out_chw, int relu,
           int H, int W)
{
    constexpr int NT  = NW*32;
    constexpr int RS  = TW + 4;
    constexpr int AP  = (ROWS + 2) * RS;
    constexpr int SMA = 32 * AP;
    constexpr int WPR = NW / ROWS;       // warps per row
    constexpr int PXW = TW / WPR;        // px per warp
    constexpr int F   = PXW / 16;        // m16 frags per warp

    extern __shared__ unsigned smu[];
    unsigned* Ah = smu;
    unsigned* Al = smu + SMA;
    unsigned* Wb = smu + 2*SMA;          // 2 buffers x 4608

    int tid = threadIdx.x;
    int lane = tid & 31, wid = tid >> 5;
    int x0 = blockIdx.x * TW;
    int y0 = blockIdx.y * ROWS;
    int Wp = W + 2;

    // stage A: fp32 -> bf16 hi/lo, ci-pair packed
    for (int i = tid; i < 16*AP; i += NT) {
        int m  = i / AP;
        int rc = i - m * AP;
        int r = rc / RS;
        int c = rc - r * RS;
        float4 v = make_float4(0.f, 0.f, 0.f, 0.f);
        if (c < TW+2 && (x0 + c) < Wp)
            v = *(const float4*)(in + (((size_t)(y0 + r))*Wp + x0 + c)*64 + m*4);
        __nv_bfloat162 h0 = __floats2bfloat162_rn(v.x, v.y);
        __nv_bfloat162 h1 = __floats2bfloat162_rn(v.z, v.w);
        __nv_bfloat162 l0 = __floats2bfloat162_rn(v.x - __bfloat162float(h0.x),
                                                  v.y - __bfloat162float(h0.y));
        __nv_bfloat162 l1 = __floats2bfloat162_rn(v.z - __bfloat162float(h1.x),
                                                  v.w - __bfloat162float(h1.y));
        Ah[(2*m  )*AP + rc] = *reinterpret_cast<unsigned*>(&h0);
        Ah[(2*m+1)*AP + rc] = *reinterpret_cast<unsigned*>(&h1);
        Al[(2*m  )*AP + rc] = *reinterpret_cast<unsigned*>(&l0);
        Al[(2*m+1)*AP + rc] = *reinterpret_cast<unsigned*>(&l1);
    }

    int yl = wid / WPR;
    int xw = (wid % WPR) * PXW;
    int qp = lane >> 2;
    int qk = lane & 3;

    float acc[F][8][4];
    #pragma unroll
    for (int f = 0; f < F; f++)
        #pragma unroll
        for (int n = 0; n < 8; n++)
            #pragma unroll
            for (int j = 0; j < 4; j++) acc[f][n][j] = 0.f;

    #pragma unroll 1
    for (int tap = 0; tap < 9; tap++) {
        // stage weights into buffer tap&1 (safe with single sync: prev-prev
        // buffer users finished before previous tap's sync)
        unsigned* Wh2 = Wb + (tap & 1) * 4608;
        unsigned* Wl2 = Wh2 + 2304;
        const uint4* ph = (const uint4*)(g_wph + ((size_t)layer*9 + tap)*2048);
        const uint4* pl = (const uint4*)(g_wpl + ((size_t)layer*9 + tap)*2048);
        for (int i = tid; i < 512; i += NT) {
            uint4 vh = ph[i], vl = pl[i];
            int pair = i >> 4, co4 = (i & 15) * 4;
            *(uint4*)&Wh2[pair*72 + co4] = vh;
            *(uint4*)&Wl2[pair*72 + co4] = vl;
        }
        __syncthreads();

        int dy = tap / 3;
        int dx = tap - 3*dy;
        int abase = (yl + dy)*RS + xw + dx + qp;

        #pragma unroll
        for (int kst = 0; kst < 4; kst++) {
            int p0 = kst*8 + qk;
            int p1 = p0 + 4;
            unsigned ah[F][4], al[F][4];
            #pragma unroll
            for (int f = 0; f < F; f++) {
                int a0b = p0*AP + abase + f*16;
                int a1b = p1*AP + abase + f*16;
                ah[f][0] = Ah[a0b];  ah[f][1] = Ah[a0b+8];
                ah[f][2] = Ah[a1b];  ah[f][3] = Ah[a1b+8];
                al[f][0] = Al[a0b];  al[f][1] = Al[a0b+8];
                al[f][2] = Al[a1b];  al[f][3] = Al[a1b+8];
            }
            int wb0 = p0*72 + qp;
            int wb1 = p1*72 + qp;
            #pragma unroll
            for (int n = 0; n < 8; n++) {
                unsigned w0 = Wh2[wb0 + n*8];
                unsigned w1 = Wh2[wb1 + n*8];
                unsigned v0 = Wl2[wb0 + n*8];
                unsigned v1 = Wl2[wb1 + n*8];
                #pragma unroll
                for (int f = 0; f < F; f++) {
                    MMA_BF16(acc[f][n][0],acc[f][n][1],acc[f][n][2],acc[f][n][3],
                             ah[f][0],ah[f][1],ah[f][2],ah[f][3], w0,w1);
                    MMA_BF16(acc[f][n][0],acc[f][n][1],acc[f][n][2],acc[f][n][3],
                             al[f][0],al[f][1],al[f][2],al[f][3], w0,w1);
                    MMA_BF16(acc[f][n][0],acc[f][n][1],acc[f][n][2],acc[f][n][3],
                             ah[f][0],ah[f][1],ah[f][2],ah[f][3], v0,v1);
                }
            }
        }
        __syncthreads();
    }

    int y = y0 + yl;
    #pragma unroll
    for (int n = 0; n < 8; n++) {
        int ch = n*8 + 2*qk;
        #pragma unroll
        for (int f = 0; f < F; f++) {
            epi_store(acc[f][n][0], acc[f][n][1], y, x0+xw+f*16+qp,   ch, add, add_pad, out, out_chw, relu, H, W);
            epi_store(acc[f][n][2], acc[f][n][3], y, x0+xw+f*16+qp+8, ch, add, add_pad, out, out_chw, relu, H, W);
        }
    }
}

#define SMEM200 ((2*32*680 + 2*4608)*4)
#define SMEM100 ((2*32*216 + 2*4608)*4)

// ---------------- bilinear 2x upsample, padded NHWC 102 -> 202 ----------------
__global__ void upsample_k(const float* __restrict__ in, float* __restrict__ out)
{
    int idx = blockIdx.x * 256 + threadIdx.x;
    if (idx >= 200*200*16) return;
    int ci4 = idx & 15;
    int p = idx >> 4;
    int x = p % 200, y = p / 200;
    float sx = 0.5f*x - 0.25f;
    float sy = 0.5f*y - 0.25f;
    float fx = floorf(sx), fy = floorf(sy);
    float tx = sx - fx, ty = sy - fy;
    int x0c = max((int)fx, 0), x1c = min((int)fx + 1, 99);
    int y0c = max((int)fy, 0), y1c = min((int)fy + 1, 99);
    float4 v00 = ((const float4*)(in + (((size_t)(y0c+1))*102 + x0c+1)*64))[ci4];
    float4 v01 = ((const float4*)(in + (((size_t)(y0c+1))*102 + x1c+1)*64))[ci4];
    float4 v10 = ((const float4*)(in + (((size_t)(y1c+1))*102 + x0c+1)*64))[ci4];
    float4 v11 = ((const float4*)(in + (((size_t)(y1c+1))*102 + x1c+1)*64))[ci4];
    float w00 = (1.f-ty)*(1.f-tx), w01 = (1.f-ty)*tx, w10 = ty*(1.f-tx), w11 = ty*tx;
    float4 r;
    r.x = w00*v00.x + w01*v01.x + w10*v10.x + w11*v11.x;
    r.y = w00*v00.y + w01*v01.y + w10*v10.y + w11*v11.y;
    r.z = w00*v00.z + w01*v01.z + w10*v10.z + w11*v11.z;
    r.w = w00*v00.w + w01*v01.w + w10*v10.w + w11*v11.w;
    ((float4*)(out + (((size_t)(y+1))*202 + x+1)*64))[ci4] = r;
}

// ---------------- instance norm (deterministic two-stage) ----------------
__global__ void in_rows_k(const float* __restrict__ x)
{
    int r = blockIdx.x;
    int c = threadIdx.x;
    const float* p = x + (size_t)r * 202 * 64;
    float s = 0.f, s2 = 0.f;
    for (int px = 0; px < 202; px++) {
        float v = p[px*64 + c];
        s += v; s2 += v*v;
    }
    g_part[r*128 + c]      = s;
    g_part[r*128 + 64 + c] = s2;
}

__global__ void in_stats_k()
{
    int c = threadIdx.x;
    float s = 0.f, s2 = 0.f;
    for (int r = 0; r < 202; r++) {
        s  += g_part[r*128 + c];
        s2 += g_part[r*128 + 64 + c];
    }
    float mu  = s * (1.f/40000.f);
    float var = s2 * (1.f/40000.f) - mu*mu;
    g_stats[c*2]   = mu;
    g_stats[c*2+1] = 1.f/sqrtf(var + 1e-5f);
}

__global__ void in_apply_k(const float* __restrict__ t, const float* __restrict__ addp,
                           float* __restrict__ out)
{
    int idx = blockIdx.x * 256 + threadIdx.x;
    if (idx >= 200*200*64) return;
    int ch = idx & 63;
    int p = idx >> 6;
    int x = p % 200, y = p / 200;
    size_t o = (((size_t)(y+1))*202 + x+1)*64 + ch;
    out[o] = (t[o] - g_stats[ch*2]) * g_stats[ch*2+1] + addp[o];
}

// ---------------- launch ----------------
extern "C" void kernel_launch(void* const* d_in, const int* in_sizes, int n_in,
                              void* d_out, int out_size)
{
    const float* features = (const float*)d_in[0];
    const float* means    = (const float*)d_in[1];
    const float* cov      = (const float*)d_in[2];
    const float* opac     = (const float*)d_in[3];
    const float* emb      = (const float*)d_in[4];
    const float* conv1w   = (const float*)d_in[5];
    const float* blkw     = (const float*)d_in[6];
    const float* upw      = (const float*)d_in[7];
    float* out = (float*)d_out;

    cudaFuncSetAttribute(conv_mma_t<16,8,64>, cudaFuncAttributeMaxDynamicSharedMemorySize, SMEM200);
    cudaFuncSetAttribute(conv_mma_t<8,4,32>,  cudaFuncAttributeMaxDynamicSharedMemorySize, SMEM100);

    float *s0a,*s0b,*s0c,*s0d,*b1,*b2,*b3,*b4;
    cudaGetSymbolAddress((void**)&s0a, g_s0a);
    cudaGetSymbolAddress((void**)&s0b, g_s0b);
    cudaGetSymbolAddress((void**)&s0c, g_s0c);
    cudaGetSymbolAddress((void**)&s0d, g_s0d);
    cudaGetSymbolAddress((void**)&b1,  g_b1);
    cudaGetSymbolAddress((void**)&b2,  g_b2);
    cudaGetSymbolAddress((void**)&b3,  g_b3);
    cudaGetSymbolAddress((void**)&b4,  g_b4);

    prep_k<<<8, 256>>>(means, cov, opac);
    numg_k<<<1, 256>>>(means, opac, out, out_size);
    prep_w<<<792, 256>>>(conv1w, blkw, upw);
    render_k<<<dim3(7,7),   256>>>(0, features, s0a, 100);
    render_k<<<dim3(13,13), 256>>>(1, features, b1, 200);

    dim3 gs0(4, 25);   // 100: x-tiles of 32, y-tiles of 4
    dim3 gs1(4, 25);   // 200: x-tiles of 64, y-tiles of 8

    // stage 0 @100x100 (layers 0..4)
    conv_mma_t<8,4,32><<<gs0, 256, SMEM100>>>(s0a, 0, emb, 0, s0b, 0, 0, 100, 100);
    conv_mma_t<8,4,32><<<gs0, 256, SMEM100>>>(s0b, 1, nullptr, 1, s0c, 0, 1, 100, 100);
    conv_mma_t<8,4,32><<<gs0, 256, SMEM100>>>(s0c, 2, s0b, 1, s0d, 0, 1, 100, 100);
    conv_mma_t<8,4,32><<<gs0, 256, SMEM100>>>(s0d, 3, nullptr, 1, s0b, 0, 1, 100, 100);
    conv_mma_t<8,4,32><<<gs0, 256, SMEM100>>>(s0b, 4, s0d, 1, s0c, 0, 1, 100, 100);

    // stage 1 @200x200 (layers 5..10)
    conv_mma_t<16,8,64><<<gs1, 512, SMEM200>>>(b1, 5, nullptr, 1, b2, 0, 0, 200, 200);
    upsample_k<<<2500, 256>>>(s0c, b3);
    conv_mma_t<16,8,64><<<gs1, 512, SMEM200>>>(b3, 6, nullptr, 1, b4, 0, 0, 200, 200);
    in_rows_k<<<202, 64>>>(b4);
    in_stats_k<<<1, 64>>>();
    in_apply_k<<<10000, 256>>>(b4, b2, b1);
    conv_mma_t<16,8,64><<<gs1, 512, SMEM200>>>(b1, 7, nullptr, 1, b3, 0, 1, 200, 200);
    conv_mma_t<16,8,64><<<gs1, 512, SMEM200>>>(b3, 8, b1, 1, b4, 0, 1, 200, 200);
    conv_mma_t<16,8,64><<<gs1, 512, SMEM200>>>(b4, 9, nullptr, 1, b3, 0, 1, 200, 200);
    conv_mma_t<16,8,64><<<gs1, 512, SMEM200>>>(b3, 10, b4, 1, out, 1, 1, 200, 200);
}